// round 1
// baseline (speedup 1.0000x reference)
#include <cuda_runtime.h>
#include <cuda_bf16.h>
#include <cstdint>

// Shapes (fixed for this problem)
#define B_DIM 256
#define D_DIM 65536
#define N_DIM 41
#define G_DIM 2048
#define O_DIM 256
#define E_DIM 512
#define NO_DIM (N_DIM * O_DIM)   // 10496
#define NEG_SLOPE 0.2f

// Scratch (device globals — no runtime allocation allowed)
__device__ float g_xT[(size_t)D_DIM * B_DIM];        // 64 MB: x transposed [D][B]
__device__ float g_HT[(size_t)NO_DIM * B_DIM];       // 10.5 MB: H transposed [N*O][B]
__device__ float g_P[(size_t)N_DIM * B_DIM * E_DIM]; // 21.5 MB: split-K partials [41][B][E]

// ---------------------------------------------------------------------------
// Kernel 1: transpose x (B x D) -> xT (D x B), 32x32 smem tiles
// ---------------------------------------------------------------------------
__global__ void transpose_kernel(const float* __restrict__ x) {
    __shared__ float tile[32][33];
    int d0 = blockIdx.x * 32;
    int b0 = blockIdx.y * 32;
    int tx = threadIdx.x;   // 0..31
    int ty = threadIdx.y;   // 0..7
#pragma unroll
    for (int i = 0; i < 32; i += 8)
        tile[ty + i][tx] = x[(size_t)(b0 + ty + i) * D_DIM + d0 + tx];
    __syncthreads();
#pragma unroll
    for (int i = 0; i < 32; i += 8)
        g_xT[(size_t)(d0 + ty + i) * B_DIM + b0 + tx] = tile[tx][ty + i];
}

// ---------------------------------------------------------------------------
// Kernel 2: fused gather + GEMM1.
//   HT[n*256+o][b] = sum_g xT[idx[n][g]][b] * W[n][g][o] + bias[n][o]
// Block: 128(b) x 128(o) tile for one n. 256 threads, 8x8 per thread, BK=16.
// ---------------------------------------------------------------------------
__global__ __launch_bounds__(256) void gemm1_kernel(
    const int*   __restrict__ gidx,   // [41][2048]
    const float* __restrict__ W,      // [41][2048][256]
    const float* __restrict__ bias)   // [41][256]
{
    const int n     = blockIdx.z;
    const int bbase = blockIdx.x * 128;
    const int obase = blockIdx.y * 128;

    __shared__ int   sIdx[G_DIM];       // 8 KB
    __shared__ float sA[16][128];       // [k][b] 8 KB
    __shared__ float sB[16][128];       // [k][o] 8 KB

    const int tid = threadIdx.x;

    // preload this n's full index row once
    const int* grow = gidx + (size_t)n * G_DIM;
    for (int i = tid; i < G_DIM; i += 256) sIdx[i] = grow[i];
    __syncthreads();

    const int tx = tid % 16;    // o micro
    const int ty = tid / 16;    // b micro
    const int lr = tid / 128;   // 0..1 (row pair for loads)
    const int lc = tid % 128;   // col for loads

    const float* Wn = W + (size_t)n * G_DIM * O_DIM;

    float acc[8][8];
#pragma unroll
    for (int i = 0; i < 8; i++)
#pragma unroll
        for (int j = 0; j < 8; j++) acc[i][j] = 0.0f;

    for (int k0 = 0; k0 < G_DIM; k0 += 16) {
#pragma unroll
        for (int i = 0; i < 16; i += 2) {
            int kk = lr + i;
            sA[kk][lc] = g_xT[(size_t)sIdx[k0 + kk] * B_DIM + bbase + lc];
            sB[kk][lc] = Wn[(size_t)(k0 + kk) * O_DIM + obase + lc];
        }
        __syncthreads();
#pragma unroll
        for (int kk = 0; kk < 16; kk++) {
            float4 a0 = *(const float4*)&sA[kk][ty * 8];
            float4 a1 = *(const float4*)&sA[kk][ty * 8 + 4];
            float4 c0 = *(const float4*)&sB[kk][tx * 8];
            float4 c1 = *(const float4*)&sB[kk][tx * 8 + 4];
            float a[8] = {a0.x, a0.y, a0.z, a0.w, a1.x, a1.y, a1.z, a1.w};
            float c[8] = {c0.x, c0.y, c0.z, c0.w, c1.x, c1.y, c1.z, c1.w};
#pragma unroll
            for (int i = 0; i < 8; i++)
#pragma unroll
                for (int j = 0; j < 8; j++) acc[i][j] += a[i] * c[j];
        }
        __syncthreads();
    }

    // epilogue: write H transposed [N*O][B], add bias
    const float* bn = bias + (size_t)n * O_DIM + obase;
#pragma unroll
    for (int j = 0; j < 8; j++) {
        int o = tx * 8 + j;
        float bv = bn[o];
        float* dst = g_HT + (size_t)(n * O_DIM + obase + o) * B_DIM + bbase + ty * 8;
        float4 v0 = make_float4(acc[0][j] + bv, acc[1][j] + bv, acc[2][j] + bv, acc[3][j] + bv);
        float4 v1 = make_float4(acc[4][j] + bv, acc[5][j] + bv, acc[6][j] + bv, acc[7][j] + bv);
        *(float4*)dst = v0;
        *(float4*)(dst + 4) = v1;
    }
}

// ---------------------------------------------------------------------------
// Kernel 3: GEMM2 split-K.
//   P[s][b][e] = sum_{k in split s} HT[k][b] * W3[k][e],   s = 0..40, 256 k each
// Block: 128(b) x 128(e), 256 threads, 8x8 per thread, BK=16.
// ---------------------------------------------------------------------------
__global__ __launch_bounds__(256) void gemm2_kernel(
    const float* __restrict__ W3)     // [10496][512]
{
    const int s     = blockIdx.z;          // k-split 0..40
    const int bbase = blockIdx.x * 128;    // B=256 -> 2
    const int ebase = blockIdx.y * 128;    // E=512 -> 4

    __shared__ float sA[16][128];   // [k][b]
    __shared__ float sB[16][128];   // [k][e]

    const int tid = threadIdx.x;
    const int tx = tid % 16;    // e micro
    const int ty = tid / 16;    // b micro
    const int lr = tid / 128;
    const int lc = tid % 128;

    float acc[8][8];
#pragma unroll
    for (int i = 0; i < 8; i++)
#pragma unroll
        for (int j = 0; j < 8; j++) acc[i][j] = 0.0f;

    const int kbeg = s * 256;
    for (int k0 = kbeg; k0 < kbeg + 256; k0 += 16) {
#pragma unroll
        for (int i = 0; i < 16; i += 2) {
            int kk = lr + i;
            sA[kk][lc] = g_HT[(size_t)(k0 + kk) * B_DIM + bbase + lc];
            sB[kk][lc] = W3[(size_t)(k0 + kk) * E_DIM + ebase + lc];
        }
        __syncthreads();
#pragma unroll
        for (int kk = 0; kk < 16; kk++) {
            float4 a0 = *(const float4*)&sA[kk][ty * 8];
            float4 a1 = *(const float4*)&sA[kk][ty * 8 + 4];
            float4 c0 = *(const float4*)&sB[kk][tx * 8];
            float4 c1 = *(const float4*)&sB[kk][tx * 8 + 4];
            float a[8] = {a0.x, a0.y, a0.z, a0.w, a1.x, a1.y, a1.z, a1.w};
            float c[8] = {c0.x, c0.y, c0.z, c0.w, c1.x, c1.y, c1.z, c1.w};
#pragma unroll
            for (int i = 0; i < 8; i++)
#pragma unroll
                for (int j = 0; j < 8; j++) acc[i][j] += a[i] * c[j];
        }
        __syncthreads();
    }

    // write partials [s][b][e], coalesced along e
    float* Ps = g_P + (size_t)s * B_DIM * E_DIM;
#pragma unroll
    for (int i = 0; i < 8; i++) {
        float* dst = Ps + (size_t)(bbase + ty * 8 + i) * E_DIM + ebase + tx * 8;
        *(float4*)dst       = make_float4(acc[i][0], acc[i][1], acc[i][2], acc[i][3]);
        *(float4*)(dst + 4) = make_float4(acc[i][4], acc[i][5], acc[i][6], acc[i][7]);
    }
}

// ---------------------------------------------------------------------------
// Kernel 4: reduce 41 partials + bias b3 + leaky ReLU -> out
// ---------------------------------------------------------------------------
__global__ void reduce_kernel(const float* __restrict__ b3, float* __restrict__ out) {
    int i = blockIdx.x * 256 + threadIdx.x;   // 0 .. 131071
    int e = i & (E_DIM - 1);
    float sum = b3[e];
#pragma unroll
    for (int s = 0; s < N_DIM; s++)
        sum += g_P[(size_t)s * B_DIM * E_DIM + i];
    out[i] = (sum >= 0.0f) ? sum : NEG_SLOPE * sum;
}

// ---------------------------------------------------------------------------
extern "C" void kernel_launch(void* const* d_in, const int* in_sizes, int n_in,
                              void* d_out, int out_size) {
    const float* x    = (const float*)d_in[0];   // [256][65536]
    const int*   gidx = (const int*)  d_in[1];   // [41][2048]
    const float* W    = (const float*)d_in[2];   // [41][2048][256]
    const float* bias = (const float*)d_in[3];   // [41][256]
    const float* W3   = (const float*)d_in[4];   // [10496][512]
    const float* b3   = (const float*)d_in[5];   // [512]
    float* out = (float*)d_out;                  // [256][512]

    // 1) transpose x -> xT
    {
        dim3 grid(D_DIM / 32, B_DIM / 32);
        dim3 block(32, 8);
        transpose_kernel<<<grid, block>>>(x);
    }
    // 2) fused gather + GEMM1 -> HT
    {
        dim3 grid(B_DIM / 128, O_DIM / 128, N_DIM);  // (2,2,41)
        gemm1_kernel<<<grid, 256>>>(gidx, W, bias);
    }
    // 3) GEMM2 split-K -> partials
    {
        dim3 grid(B_DIM / 128, E_DIM / 128, N_DIM);  // (2,4,41)
        gemm2_kernel<<<grid, 256>>>(W3);
    }
    // 4) reduce + bias + leaky ReLU -> out
    {
        reduce_kernel<<<(B_DIM * E_DIM) / 256, 256>>>(b3, out);
    }
}

// round 2
// speedup vs baseline: 2.3736x; 2.3736x over previous
#include <cuda_runtime.h>
#include <cuda_bf16.h>
#include <cstdint>

#define B_DIM 256
#define D_DIM 65536
#define N_DIM 41
#define G_DIM 2048
#define O_DIM 256
#define E_DIM 512
#define NO_DIM (N_DIM * O_DIM)   // 10496
#define NEG_SLOPE 0.2f

// Scratch (device globals)
__device__ float g_xT[(size_t)D_DIM * B_DIM];        // 64 MB: x^T [D][B]
__device__ float g_H [(size_t)B_DIM * NO_DIM];       // 10.5 MB: H row-major [B][N*O]
__device__ float g_P [(size_t)N_DIM * B_DIM * E_DIM];// 21.5 MB: split-K partials

// ---------------------------------------------------------------- helpers
__device__ __forceinline__ uint32_t sptr(const void* p) {
    return (uint32_t)__cvta_generic_to_shared(p);
}
__device__ __forceinline__ void bsplit(float v, unsigned short& h, unsigned short& l) {
    __nv_bfloat16 bh = __float2bfloat16_rn(v);
    h = __bfloat16_as_ushort(bh);
    l = __bfloat16_as_ushort(__float2bfloat16_rn(v - __bfloat162float(bh)));
}
__device__ __forceinline__ void split_store8(float4 v, unsigned short* dhi, unsigned short* dlo) {
    unsigned short h0,h1,h2,h3,l0,l1,l2,l3;
    bsplit(v.x,h0,l0); bsplit(v.y,h1,l1); bsplit(v.z,h2,l2); bsplit(v.w,h3,l3);
    *(uint2*)dhi = make_uint2((uint32_t)h0 | ((uint32_t)h1<<16), (uint32_t)h2 | ((uint32_t)h3<<16));
    *(uint2*)dlo = make_uint2((uint32_t)l0 | ((uint32_t)l1<<16), (uint32_t)l2 | ((uint32_t)l3<<16));
}
__device__ __forceinline__ void ldsm4t(uint32_t* r, uint32_t a) {
    asm volatile("ldmatrix.sync.aligned.m8n8.x4.trans.shared.b16 {%0,%1,%2,%3},[%4];"
                 : "=r"(r[0]), "=r"(r[1]), "=r"(r[2]), "=r"(r[3]) : "r"(a));
}
__device__ __forceinline__ void ldsm4(uint32_t* r, uint32_t a) {
    asm volatile("ldmatrix.sync.aligned.m8n8.x4.shared.b16 {%0,%1,%2,%3},[%4];"
                 : "=r"(r[0]), "=r"(r[1]), "=r"(r[2]), "=r"(r[3]) : "r"(a));
}
__device__ __forceinline__ void mma16816(float* c, const uint32_t* a, const uint32_t* b) {
    asm volatile("mma.sync.aligned.m16n8k16.row.col.f32.bf16.bf16.f32 "
                 "{%0,%1,%2,%3},{%4,%5,%6,%7},{%8,%9},{%0,%1,%2,%3};"
                 : "+f"(c[0]), "+f"(c[1]), "+f"(c[2]), "+f"(c[3])
                 : "r"(a[0]), "r"(a[1]), "r"(a[2]), "r"(a[3]), "r"(b[0]), "r"(b[1]));
}

// ---------------------------------------------------------------- transpose
__global__ __launch_bounds__(256) void transpose_kernel(const float* __restrict__ x) {
    __shared__ float tile[64][65];
    int d0 = blockIdx.x * 64, b0 = blockIdx.y * 64;
    int t = threadIdx.x;
    int br = t / 16, dc = (t % 16) * 4;
#pragma unroll
    for (int p = 0; p < 4; p++) {
        int b = br + p * 16;
        float4 v = *(const float4*)&x[(size_t)(b0 + b) * D_DIM + d0 + dc];
        tile[b][dc] = v.x; tile[b][dc+1] = v.y; tile[b][dc+2] = v.z; tile[b][dc+3] = v.w;
    }
    __syncthreads();
    int dr = t / 16, bc = (t % 16) * 4;
#pragma unroll
    for (int p = 0; p < 4; p++) {
        int d = dr + p * 16;
        float4 v = make_float4(tile[bc][d], tile[bc+1][d], tile[bc+2][d], tile[bc+3][d]);
        *(float4*)&g_xT[(size_t)(d0 + d) * B_DIM + b0 + bc] = v;
    }
}

// ---------------------------------------------------------------- GEMM1
// H[b][n*256+o] = sum_g xT[idx[n][g]][b] * W[n][g][o] + bias[n][o]
// block tile 128(b=m) x 128(o=n), k-chunk 16, 8 warps (2m x 4n), warp 64x32
__global__ __launch_bounds__(256, 1) void gemm1_kernel(
    const int* __restrict__ gidx, const float* __restrict__ W, const float* __restrict__ bias)
{
    const int n     = blockIdx.z;
    const int bbase = blockIdx.x * 128;
    const int obase = blockIdx.y * 128;

    __shared__ int sIdx[G_DIM];
    __shared__ unsigned short As[2][2][16][136];  // [buf][hi/lo][k][m]
    __shared__ unsigned short Bs[2][2][16][136];  // [buf][hi/lo][k][o]

    const int tid = threadIdx.x, lane = tid & 31, warp = tid >> 5;
    const int wm = (warp & 1) * 64, wn = (warp >> 1) * 32;

    const int* grow = gidx + (size_t)n * G_DIM;
    for (int i = tid; i < G_DIM; i += 256) sIdx[i] = grow[i];
    __syncthreads();

    const float* Wn = W + (size_t)n * G_DIM * O_DIM;
    const int kk  = tid >> 5;        // 0..7
    const int col = (tid & 31) * 4;  // 0..124

    // ldmatrix lane address components
    const int g8 = lane >> 3, i8 = lane & 7;
    const int a_krow = (g8 >> 1) * 8 + i8, a_mcol = (g8 & 1) * 8;
    const int b_krow = (g8 & 1) * 8 + i8, b_ncol = (g8 >> 1) * 8;

    float acc[4][4][4];
#pragma unroll
    for (int i = 0; i < 4; i++)
#pragma unroll
        for (int j = 0; j < 4; j++)
#pragma unroll
            for (int q = 0; q < 4; q++) acc[i][j][q] = 0.0f;

    float4 pa0, pa1, pb0, pb1;
    {
        int r0 = sIdx[kk], r1 = sIdx[kk + 8];
        pa0 = *(const float4*)&g_xT[(size_t)r0 * B_DIM + bbase + col];
        pa1 = *(const float4*)&g_xT[(size_t)r1 * B_DIM + bbase + col];
        pb0 = *(const float4*)&Wn[(size_t)kk * O_DIM + obase + col];
        pb1 = *(const float4*)&Wn[(size_t)(kk + 8) * O_DIM + obase + col];
    }
    int buf = 0;
    split_store8(pa0, &As[buf][0][kk][col],   &As[buf][1][kk][col]);
    split_store8(pa1, &As[buf][0][kk+8][col], &As[buf][1][kk+8][col]);
    split_store8(pb0, &Bs[buf][0][kk][col],   &Bs[buf][1][kk][col]);
    split_store8(pb1, &Bs[buf][0][kk+8][col], &Bs[buf][1][kk+8][col]);
    __syncthreads();

    const int NCHUNK = G_DIM / 16;  // 128
    for (int ch = 0; ch < NCHUNK; ch++) {
        if (ch + 1 < NCHUNK) {
            int k0 = (ch + 1) * 16;
            int r0 = sIdx[k0 + kk], r1 = sIdx[k0 + kk + 8];
            pa0 = *(const float4*)&g_xT[(size_t)r0 * B_DIM + bbase + col];
            pa1 = *(const float4*)&g_xT[(size_t)r1 * B_DIM + bbase + col];
            pb0 = *(const float4*)&Wn[(size_t)(k0 + kk) * O_DIM + obase + col];
            pb1 = *(const float4*)&Wn[(size_t)(k0 + kk + 8) * O_DIM + obase + col];
        }
        // compute on buf
        uint32_t af[2][4][4], bfv[2][2][4];
#pragma unroll
        for (int v = 0; v < 2; v++)
#pragma unroll
            for (int mt = 0; mt < 4; mt++)
                ldsm4t(af[v][mt], sptr(&As[buf][v][a_krow][wm + mt * 16 + a_mcol]));
#pragma unroll
        for (int v = 0; v < 2; v++)
#pragma unroll
            for (int np = 0; np < 2; np++)
                ldsm4t(bfv[v][np], sptr(&Bs[buf][v][b_krow][wn + np * 16 + b_ncol]));
#pragma unroll
        for (int mt = 0; mt < 4; mt++)
#pragma unroll
            for (int nt = 0; nt < 4; nt++) {
                const uint32_t* bh = &bfv[0][nt >> 1][(nt & 1) * 2];
                const uint32_t* bl = &bfv[1][nt >> 1][(nt & 1) * 2];
                mma16816(acc[mt][nt], af[0][mt], bh);
                mma16816(acc[mt][nt], af[0][mt], bl);
                mma16816(acc[mt][nt], af[1][mt], bh);
            }
        if (ch + 1 < NCHUNK) {
            buf ^= 1;
            split_store8(pa0, &As[buf][0][kk][col],   &As[buf][1][kk][col]);
            split_store8(pa1, &As[buf][0][kk+8][col], &As[buf][1][kk+8][col]);
            split_store8(pb0, &Bs[buf][0][kk][col],   &Bs[buf][1][kk][col]);
            split_store8(pb1, &Bs[buf][0][kk+8][col], &Bs[buf][1][kk+8][col]);
            __syncthreads();
        }
    }

    // epilogue: H[b][n*256 + o] += bias
    const int r = lane >> 2, c = (lane & 3) * 2;
#pragma unroll
    for (int mt = 0; mt < 4; mt++) {
#pragma unroll
        for (int nt = 0; nt < 4; nt++) {
            int ocol = obase + wn + nt * 8 + c;           // 0..255 within n
            float bv0 = bias[n * O_DIM + ocol];
            float bv1 = bias[n * O_DIM + ocol + 1];
            int b0 = bbase + wm + mt * 16 + r;
            size_t base = (size_t)b0 * NO_DIM + (size_t)n * O_DIM + ocol;
            *(float2*)&g_H[base] = make_float2(acc[mt][nt][0] + bv0, acc[mt][nt][1] + bv1);
            size_t base2 = base + (size_t)8 * NO_DIM;
            *(float2*)&g_H[base2] = make_float2(acc[mt][nt][2] + bv0, acc[mt][nt][3] + bv1);
        }
    }
}

// ---------------------------------------------------------------- GEMM2 (split-K over 41 chunks of 256)
// P[s][b][e] = sum_{k in s} H[b][k] * W3[k][e]
__global__ __launch_bounds__(256, 1) void gemm2_kernel(const float* __restrict__ W3)
{
    const int s     = blockIdx.z;
    const int bbase = blockIdx.x * 128;
    const int ebase = blockIdx.y * 128;

    __shared__ unsigned short As[2][2][128][24];  // [buf][hi/lo][m][k] pitch 24
    __shared__ unsigned short Bs[2][2][16][136];  // [buf][hi/lo][k][e]

    const int tid = threadIdx.x, lane = tid & 31, warp = tid >> 5;
    const int wm = (warp & 1) * 64, wn = (warp >> 1) * 32;

    const int am  = tid >> 1;       // 0..127
    const int akg = tid & 1;        // k-half
    const int kk  = tid >> 5;
    const int col = (tid & 31) * 4;

    const int g8 = lane >> 3, i8 = lane & 7;
    const int a_mrow = (g8 & 1) * 8 + i8, a_kcol = (g8 >> 1) * 8;  // non-trans A
    const int b_krow = (g8 & 1) * 8 + i8, b_ncol = (g8 >> 1) * 8;

    float acc[4][4][4];
#pragma unroll
    for (int i = 0; i < 4; i++)
#pragma unroll
        for (int j = 0; j < 4; j++)
#pragma unroll
            for (int q = 0; q < 4; q++) acc[i][j][q] = 0.0f;

    const int kbeg = s * 256;
    float4 pa0, pa1, pb0, pb1;
    {
        const float* hrow = &g_H[(size_t)(bbase + am) * NO_DIM + kbeg + akg * 8];
        pa0 = *(const float4*)hrow;
        pa1 = *(const float4*)(hrow + 4);
        pb0 = *(const float4*)&W3[(size_t)(kbeg + kk) * E_DIM + ebase + col];
        pb1 = *(const float4*)&W3[(size_t)(kbeg + kk + 8) * E_DIM + ebase + col];
    }
    int buf = 0;
    split_store8(pa0, &As[buf][0][am][akg*8],   &As[buf][1][am][akg*8]);
    split_store8(pa1, &As[buf][0][am][akg*8+4], &As[buf][1][am][akg*8+4]);
    split_store8(pb0, &Bs[buf][0][kk][col],     &Bs[buf][1][kk][col]);
    split_store8(pb1, &Bs[buf][0][kk+8][col],   &Bs[buf][1][kk+8][col]);
    __syncthreads();

    const int NCHUNK = 16;
    for (int ch = 0; ch < NCHUNK; ch++) {
        if (ch + 1 < NCHUNK) {
            int k0 = kbeg + (ch + 1) * 16;
            const float* hrow = &g_H[(size_t)(bbase + am) * NO_DIM + k0 + akg * 8];
            pa0 = *(const float4*)hrow;
            pa1 = *(const float4*)(hrow + 4);
            pb0 = *(const float4*)&W3[(size_t)(k0 + kk) * E_DIM + ebase + col];
            pb1 = *(const float4*)&W3[(size_t)(k0 + kk + 8) * E_DIM + ebase + col];
        }
        uint32_t af[2][4][4], bfv[2][2][4];
#pragma unroll
        for (int v = 0; v < 2; v++)
#pragma unroll
            for (int mt = 0; mt < 4; mt++)
                ldsm4(af[v][mt], sptr(&As[buf][v][wm + mt * 16 + a_mrow][a_kcol]));
#pragma unroll
        for (int v = 0; v < 2; v++)
#pragma unroll
            for (int np = 0; np < 2; np++)
                ldsm4t(bfv[v][np], sptr(&Bs[buf][v][b_krow][wn + np * 16 + b_ncol]));
#pragma unroll
        for (int mt = 0; mt < 4; mt++)
#pragma unroll
            for (int nt = 0; nt < 4; nt++) {
                const uint32_t* bh = &bfv[0][nt >> 1][(nt & 1) * 2];
                const uint32_t* bl = &bfv[1][nt >> 1][(nt & 1) * 2];
                mma16816(acc[mt][nt], af[0][mt], bh);
                mma16816(acc[mt][nt], af[0][mt], bl);
                mma16816(acc[mt][nt], af[1][mt], bh);
            }
        if (ch + 1 < NCHUNK) {
            buf ^= 1;
            int k0 = kbeg + (ch + 1) * 16;
            (void)k0;
            split_store8(pa0, &As[buf][0][am][akg*8],   &As[buf][1][am][akg*8]);
            split_store8(pa1, &As[buf][0][am][akg*8+4], &As[buf][1][am][akg*8+4]);
            split_store8(pb0, &Bs[buf][0][kk][col],     &Bs[buf][1][kk][col]);
            split_store8(pb1, &Bs[buf][0][kk+8][col],   &Bs[buf][1][kk+8][col]);
            __syncthreads();
        }
    }

    // epilogue -> partials
    float* Ps = g_P + (size_t)s * B_DIM * E_DIM;
    const int r = lane >> 2, c = (lane & 3) * 2;
#pragma unroll
    for (int mt = 0; mt < 4; mt++) {
#pragma unroll
        for (int nt = 0; nt < 4; nt++) {
            int ecol = ebase + wn + nt * 8 + c;
            int b0 = bbase + wm + mt * 16 + r;
            *(float2*)&Ps[(size_t)b0 * E_DIM + ecol] =
                make_float2(acc[mt][nt][0], acc[mt][nt][1]);
            *(float2*)&Ps[(size_t)(b0 + 8) * E_DIM + ecol] =
                make_float2(acc[mt][nt][2], acc[mt][nt][3]);
        }
    }
}

// ---------------------------------------------------------------- reduce
__global__ __launch_bounds__(256) void reduce_kernel(const float* __restrict__ b3, float* __restrict__ out) {
    int i4 = blockIdx.x * 256 + threadIdx.x;       // 0..32767 float4s
    int e4 = i4 & (E_DIM / 4 - 1);
    float4 sum = ((const float4*)b3)[e4];
#pragma unroll
    for (int s = 0; s < N_DIM; s++) {
        float4 p = ((const float4*)g_P)[(size_t)s * (B_DIM * E_DIM / 4) + i4];
        sum.x += p.x; sum.y += p.y; sum.z += p.z; sum.w += p.w;
    }
    sum.x = (sum.x >= 0.f) ? sum.x : NEG_SLOPE * sum.x;
    sum.y = (sum.y >= 0.f) ? sum.y : NEG_SLOPE * sum.y;
    sum.z = (sum.z >= 0.f) ? sum.z : NEG_SLOPE * sum.z;
    sum.w = (sum.w >= 0.f) ? sum.w : NEG_SLOPE * sum.w;
    ((float4*)out)[i4] = sum;
}

// ----------------------------------------------------------------
extern "C" void kernel_launch(void* const* d_in, const int* in_sizes, int n_in,
                              void* d_out, int out_size) {
    const float* x    = (const float*)d_in[0];
    const int*   gidx = (const int*)  d_in[1];
    const float* W    = (const float*)d_in[2];
    const float* bias = (const float*)d_in[3];
    const float* W3   = (const float*)d_in[4];
    const float* b3   = (const float*)d_in[5];
    float* out = (float*)d_out;

    {
        dim3 grid(D_DIM / 64, B_DIM / 64);
        transpose_kernel<<<grid, 256>>>(x);
    }
    {
        dim3 grid(B_DIM / 128, O_DIM / 128, N_DIM);   // (2,2,41)
        gemm1_kernel<<<grid, 256>>>(gidx, W, bias);
    }
    {
        dim3 grid(B_DIM / 128, E_DIM / 128, N_DIM);   // (2,4,41)
        gemm2_kernel<<<grid, 256>>>(W3);
    }
    {
        reduce_kernel<<<(B_DIM * E_DIM / 4) / 256, 256>>>(b3, out);
    }
}

// round 5
// speedup vs baseline: 2.4876x; 1.0481x over previous
#include <cuda_runtime.h>
#include <cuda_bf16.h>
#include <cstdint>

#define B_DIM 256
#define D_DIM 65536
#define N_DIM 41
#define G_DIM 2048
#define O_DIM 256
#define E_DIM 512
#define NO_DIM (N_DIM * O_DIM)   // 10496
#define NEG_SLOPE 0.2f

// Scratch (device globals, POD types only, total ~96.25 MB == proven round-2 level)
__device__ unsigned short g_xT_hi[(size_t)D_DIM * B_DIM];   // 32 MB
__device__ unsigned short g_xT_lo[(size_t)D_DIM * B_DIM];   // 32 MB
__device__ unsigned short g_H_hi[(size_t)B_DIM * NO_DIM];   // 5.4 MB
__device__ unsigned short g_H_lo[(size_t)B_DIM * NO_DIM];   // 5.4 MB
__device__ float g_P[(size_t)N_DIM * B_DIM * E_DIM];        // 21.5 MB

// ---------------------------------------------------------------- helpers
__device__ __forceinline__ uint32_t sptr(const void* p) {
    return (uint32_t)__cvta_generic_to_shared(p);
}
__device__ __forceinline__ void fsplit(float v, unsigned short& h, unsigned short& l) {
    __nv_bfloat16 bh = __float2bfloat16_rn(v);
    h = __bfloat16_as_ushort(bh);
    l = __bfloat16_as_ushort(__float2bfloat16_rn(v - __bfloat162float(bh)));
}
__device__ __forceinline__ void split_store8(float4 v, unsigned short* dhi, unsigned short* dlo) {
    unsigned short h0,h1,h2,h3,l0,l1,l2,l3;
    bsplitcall: ;
    fsplit(v.x,h0,l0); fsplit(v.y,h1,l1); fsplit(v.z,h2,l2); fsplit(v.w,h3,l3);
    *(uint2*)dhi = make_uint2((uint32_t)h0 | ((uint32_t)h1<<16), (uint32_t)h2 | ((uint32_t)h3<<16));
    *(uint2*)dlo = make_uint2((uint32_t)l0 | ((uint32_t)l1<<16), (uint32_t)l2 | ((uint32_t)l3<<16));
}
__device__ __forceinline__ void ldsm4t(uint32_t* r, uint32_t a) {
    asm volatile("ldmatrix.sync.aligned.m8n8.x4.trans.shared.b16 {%0,%1,%2,%3},[%4];"
                 : "=r"(r[0]), "=r"(r[1]), "=r"(r[2]), "=r"(r[3]) : "r"(a));
}
__device__ __forceinline__ void ldsm4(uint32_t* r, uint32_t a) {
    asm volatile("ldmatrix.sync.aligned.m8n8.x4.shared.b16 {%0,%1,%2,%3},[%4];"
                 : "=r"(r[0]), "=r"(r[1]), "=r"(r[2]), "=r"(r[3]) : "r"(a));
}
__device__ __forceinline__ void mma16816(float* c, const uint32_t* a, const uint32_t* b) {
    asm volatile("mma.sync.aligned.m16n8k16.row.col.f32.bf16.bf16.f32 "
                 "{%0,%1,%2,%3},{%4,%5,%6,%7},{%8,%9},{%0,%1,%2,%3};"
                 : "+f"(c[0]), "+f"(c[1]), "+f"(c[2]), "+f"(c[3])
                 : "r"(a[0]), "r"(a[1]), "r"(a[2]), "r"(a[3]), "r"(b[0]), "r"(b[1]));
}

// ---------------------------------------------------------------- transpose + split x
__global__ __launch_bounds__(256) void transpose_split_kernel(const float* __restrict__ x) {
    __shared__ float tile[64][65];
    int d0 = blockIdx.x * 64, b0 = blockIdx.y * 64;
    int t = threadIdx.x;
    int br = t / 16, dc = (t % 16) * 4;
#pragma unroll
    for (int p = 0; p < 4; p++) {
        int b = br + p * 16;
        float4 v = *(const float4*)&x[(size_t)(b0 + b) * D_DIM + d0 + dc];
        tile[b][dc] = v.x; tile[b][dc+1] = v.y; tile[b][dc+2] = v.z; tile[b][dc+3] = v.w;
    }
    __syncthreads();
    int dr = t / 16, bc = (t % 16) * 4;
#pragma unroll
    for (int p = 0; p < 4; p++) {
        int d = dr + p * 16;
        unsigned short h0,h1,h2,h3,l0,l1,l2,l3;
        fsplit(tile[bc][d],   h0, l0);
        fsplit(tile[bc+1][d], h1, l1);
        fsplit(tile[bc+2][d], h2, l2);
        fsplit(tile[bc+3][d], h3, l3);
        size_t off = (size_t)(d0 + d) * B_DIM + b0 + bc;
        *(uint2*)&g_xT_hi[off] = make_uint2((uint32_t)h0 | ((uint32_t)h1<<16),
                                            (uint32_t)h2 | ((uint32_t)h3<<16));
        *(uint2*)&g_xT_lo[off] = make_uint2((uint32_t)l0 | ((uint32_t)l1<<16),
                                            (uint32_t)l2 | ((uint32_t)l3<<16));
    }
}

// ---------------------------------------------------------------- GEMM1
// H[b][n*256+o] = sum_g xT[idx[n][g]][b] * W[n][g][o] + bias[n][o]
// A from pre-split bf16 xT (no conversion); B split from fp32 W in-kernel (round-2 path).
__global__ __launch_bounds__(256, 1) void gemm1_kernel(
    const int* __restrict__ gidx, const float* __restrict__ W, const float* __restrict__ bias)
{
    __shared__ int sIdx[G_DIM];                                   // 8 KB
    __shared__ alignas(16) unsigned short As[2][2][16][136];      // 17 KB
    __shared__ alignas(16) unsigned short Bs[2][2][16][136];      // 17 KB

    const int n     = blockIdx.z;
    const int bbase = blockIdx.x * 128;
    const int obase = blockIdx.y * 128;
    const int tid = threadIdx.x, lane = tid & 31, warp = tid >> 5;
    const int wm = (warp & 1) * 64, wn = (warp >> 1) * 32;

    // A loaders: 16 rows x 16 col-chunks of 8 bf16
    const int lrowA = tid >> 4;          // 0..15
    const int lcolA = (tid & 15) * 8;    // 0..120
    // B loaders (round-2 pattern): rows kk, kk+8; 4 fp32 cols each
    const int kkB  = tid >> 5;           // 0..7
    const int colB = (tid & 31) * 4;     // 0..124

    const int* grow = gidx + (size_t)n * G_DIM;
    for (int i = tid; i < G_DIM; i += 256) sIdx[i] = grow[i];
    __syncthreads();

    const float* Wn = W + (size_t)n * G_DIM * O_DIM;

    const int g8 = lane >> 3, i8 = lane & 7;
    const int a_krow = (g8 >> 1) * 8 + i8, a_mcol = (g8 & 1) * 8;
    const int b_krow = (g8 & 1) * 8 + i8, b_ncol = (g8 >> 1) * 8;

    float acc[4][4][4];
#pragma unroll
    for (int i = 0; i < 4; i++)
#pragma unroll
        for (int j = 0; j < 4; j++)
#pragma unroll
            for (int q = 0; q < 4; q++) acc[i][j][q] = 0.0f;

    uint4 ra_h, ra_l;
    float4 pb0, pb1;
    {
        int gi = sIdx[lrowA];
        ra_h = *(const uint4*)&g_xT_hi[(size_t)gi * B_DIM + bbase + lcolA];
        ra_l = *(const uint4*)&g_xT_lo[(size_t)gi * B_DIM + bbase + lcolA];
        pb0 = *(const float4*)&Wn[(size_t)kkB * O_DIM + obase + colB];
        pb1 = *(const float4*)&Wn[(size_t)(kkB + 8) * O_DIM + obase + colB];
    }
    int buf = 0;
    *(uint4*)&As[buf][0][lrowA][lcolA] = ra_h;
    *(uint4*)&As[buf][1][lrowA][lcolA] = ra_l;
    split_store8(pb0, &Bs[buf][0][kkB][colB],   &Bs[buf][1][kkB][colB]);
    split_store8(pb1, &Bs[buf][0][kkB+8][colB], &Bs[buf][1][kkB+8][colB]);
    __syncthreads();

    const int NCHUNK = G_DIM / 16;  // 128
    for (int ch = 0; ch < NCHUNK; ch++) {
        if (ch + 1 < NCHUNK) {
            int k0 = (ch + 1) * 16;
            int gi = sIdx[k0 + lrowA];
            ra_h = *(const uint4*)&g_xT_hi[(size_t)gi * B_DIM + bbase + lcolA];
            ra_l = *(const uint4*)&g_xT_lo[(size_t)gi * B_DIM + bbase + lcolA];
            pb0 = *(const float4*)&Wn[(size_t)(k0 + kkB) * O_DIM + obase + colB];
            pb1 = *(const float4*)&Wn[(size_t)(k0 + kkB + 8) * O_DIM + obase + colB];
        }
        uint32_t af[2][4][4], bfv[2][2][4];
#pragma unroll
        for (int v = 0; v < 2; v++)
#pragma unroll
            for (int mt = 0; mt < 4; mt++)
                ldsm4t(af[v][mt], sptr(&As[buf][v][a_krow][wm + mt * 16 + a_mcol]));
#pragma unroll
        for (int v = 0; v < 2; v++)
#pragma unroll
            for (int np = 0; np < 2; np++)
                ldsm4t(bfv[v][np], sptr(&Bs[buf][v][b_krow][wn + np * 16 + b_ncol]));
#pragma unroll
        for (int mt = 0; mt < 4; mt++)
#pragma unroll
            for (int nt = 0; nt < 4; nt++) {
                const uint32_t* bh = &bfv[0][nt >> 1][(nt & 1) * 2];
                const uint32_t* bl = &bfv[1][nt >> 1][(nt & 1) * 2];
                mma16816(acc[mt][nt], af[0][mt], bh);
                mma16816(acc[mt][nt], af[0][mt], bl);
                mma16816(acc[mt][nt], af[1][mt], bh);
            }
        if (ch + 1 < NCHUNK) {
            buf ^= 1;
            *(uint4*)&As[buf][0][lrowA][lcolA] = ra_h;
            *(uint4*)&As[buf][1][lrowA][lcolA] = ra_l;
            split_store8(pb0, &Bs[buf][0][kkB][colB],   &Bs[buf][1][kkB][colB]);
            split_store8(pb1, &Bs[buf][0][kkB+8][colB], &Bs[buf][1][kkB+8][colB]);
            __syncthreads();
        }
    }

    // epilogue: H -> (hi,lo) bf16, row-major [B][NO]
    const int r = lane >> 2, c = (lane & 3) * 2;
#pragma unroll
    for (int mt = 0; mt < 4; mt++) {
#pragma unroll
        for (int nt = 0; nt < 4; nt++) {
            int ocol = obase + wn + nt * 8 + c;
            float bv0 = bias[n * O_DIM + ocol];
            float bv1 = bias[n * O_DIM + ocol + 1];
            int b0 = bbase + wm + mt * 16 + r;
#pragma unroll
            for (int q = 0; q < 2; q++) {
                float h0 = acc[mt][nt][q*2]   + bv0;
                float h1 = acc[mt][nt][q*2+1] + bv1;
                unsigned short hh0, hl0, hh1, hl1;
                fsplit(h0, hh0, hl0);
                fsplit(h1, hh1, hl1);
                size_t base = (size_t)(b0 + q*8) * NO_DIM + (size_t)n * O_DIM + ocol;
                *(uint32_t*)&g_H_hi[base] = (uint32_t)hh0 | ((uint32_t)hh1 << 16);
                *(uint32_t*)&g_H_lo[base] = (uint32_t)hl0 | ((uint32_t)hl1 << 16);
            }
        }
    }
}

// ---------------------------------------------------------------- GEMM2 split-K
// P[s][b][e] = sum_{k in split s} H[b][k] * W3[k][e]
// A from pre-split bf16 H; B split from fp32 W3 in-kernel (round-2 path).
__global__ __launch_bounds__(256, 1) void gemm2_kernel(const float* __restrict__ W3)
{
    __shared__ alignas(16) unsigned short As[2][2][128][24];   // 24 KB  [m][k]
    __shared__ alignas(16) unsigned short Bs[2][2][16][136];   // 17 KB  [k][e]

    const int s     = blockIdx.z;
    const int bbase = blockIdx.x * 128;
    const int ebase = blockIdx.y * 128;
    const int tid = threadIdx.x, lane = tid & 31, warp = tid >> 5;
    const int wm = (warp & 1) * 64, wn = (warp >> 1) * 32;

    const int arow = tid >> 1, ahalf = (tid & 1) * 8;   // A: 128 rows x 2 chunks of 8
    const int kkB  = tid >> 5, colB = (tid & 31) * 4;   // B: round-2 pattern

    const int g8 = lane >> 3, i8 = lane & 7;
    const int a_mrow = (g8 & 1) * 8 + i8, a_kcol = (g8 >> 1) * 8;
    const int b_krow = (g8 & 1) * 8 + i8, b_ncol = (g8 >> 1) * 8;

    float acc[4][4][4];
#pragma unroll
    for (int i = 0; i < 4; i++)
#pragma unroll
        for (int j = 0; j < 4; j++)
#pragma unroll
            for (int q = 0; q < 4; q++) acc[i][j][q] = 0.0f;

    const int kbeg = s * 256;
    uint4 ra_h, ra_l;
    float4 pb0, pb1;
    {
        ra_h = *(const uint4*)&g_H_hi[(size_t)(bbase + arow) * NO_DIM + kbeg + ahalf];
        ra_l = *(const uint4*)&g_H_lo[(size_t)(bbase + arow) * NO_DIM + kbeg + ahalf];
        pb0 = *(const float4*)&W3[(size_t)(kbeg + kkB) * E_DIM + ebase + colB];
        pb1 = *(const float4*)&W3[(size_t)(kbeg + kkB + 8) * E_DIM + ebase + colB];
    }
    int buf = 0;
    *(uint4*)&As[buf][0][arow][ahalf] = ra_h;
    *(uint4*)&As[buf][1][arow][ahalf] = ra_l;
    split_store8(pb0, &Bs[buf][0][kkB][colB],   &Bs[buf][1][kkB][colB]);
    split_store8(pb1, &Bs[buf][0][kkB+8][colB], &Bs[buf][1][kkB+8][colB]);
    __syncthreads();

    const int NCHUNK = 16;
    for (int ch = 0; ch < NCHUNK; ch++) {
        if (ch + 1 < NCHUNK) {
            int k0 = kbeg + (ch + 1) * 16;
            ra_h = *(const uint4*)&g_H_hi[(size_t)(bbase + arow) * NO_DIM + k0 + ahalf];
            ra_l = *(const uint4*)&g_H_lo[(size_t)(bbase + arow) * NO_DIM + k0 + ahalf];
            pb0 = *(const float4*)&W3[(size_t)(k0 + kkB) * E_DIM + ebase + colB];
            pb1 = *(const float4*)&W3[(size_t)(k0 + kkB + 8) * E_DIM + ebase + colB];
        }
        uint32_t af[2][4][4], bfv[2][2][4];
#pragma unroll
        for (int v = 0; v < 2; v++)
#pragma unroll
            for (int mt = 0; mt < 4; mt++)
                ldsm4(af[v][mt], sptr(&As[buf][v][wm + mt * 16 + a_mrow][a_kcol]));
#pragma unroll
        for (int v = 0; v < 2; v++)
#pragma unroll
            for (int np = 0; np < 2; np++)
                ldsm4t(bfv[v][np], sptr(&Bs[buf][v][b_krow][wn + np * 16 + b_ncol]));
#pragma unroll
        for (int mt = 0; mt < 4; mt++)
#pragma unroll
            for (int nt = 0; nt < 4; nt++) {
                const uint32_t* bh = &bfv[0][nt >> 1][(nt & 1) * 2];
                const uint32_t* bl = &bfv[1][nt >> 1][(nt & 1) * 2];
                mma16816(acc[mt][nt], af[0][mt], bh);
                mma16816(acc[mt][nt], af[0][mt], bl);
                mma16816(acc[mt][nt], af[1][mt], bh);
            }
        if (ch + 1 < NCHUNK) {
            buf ^= 1;
            *(uint4*)&As[buf][0][arow][ahalf] = ra_h;
            *(uint4*)&As[buf][1][arow][ahalf] = ra_l;
            split_store8(pb0, &Bs[buf][0][kkB][colB],   &Bs[buf][1][kkB][colB]);
            split_store8(pb1, &Bs[buf][0][kkB+8][colB], &Bs[buf][1][kkB+8][colB]);
            __syncthreads();
        }
    }

    float* Ps = g_P + (size_t)s * B_DIM * E_DIM;
    const int r = lane >> 2, c = (lane & 3) * 2;
#pragma unroll
    for (int mt = 0; mt < 4; mt++) {
#pragma unroll
        for (int nt = 0; nt < 4; nt++) {
            int ecol = ebase + wn + nt * 8 + c;
            int b0 = bbase + wm + mt * 16 + r;
            *(float2*)&Ps[(size_t)b0 * E_DIM + ecol] =
                make_float2(acc[mt][nt][0], acc[mt][nt][1]);
            *(float2*)&Ps[(size_t)(b0 + 8) * E_DIM + ecol] =
                make_float2(acc[mt][nt][2], acc[mt][nt][3]);
        }
    }
}

// ---------------------------------------------------------------- reduce
__global__ __launch_bounds__(256) void reduce_kernel(const float* __restrict__ b3, float* __restrict__ out) {
    int i4 = blockIdx.x * 256 + threadIdx.x;
    int e4 = i4 & (E_DIM / 4 - 1);
    float4 sum = ((const float4*)b3)[e4];
#pragma unroll
    for (int s = 0; s < N_DIM; s++) {
        float4 p = ((const float4*)g_P)[(size_t)s * (B_DIM * E_DIM / 4) + i4];
        sum.x += p.x; sum.y += p.y; sum.z += p.z; sum.w += p.w;
    }
    sum.x = (sum.x >= 0.f) ? sum.x : NEG_SLOPE * sum.x;
    sum.y = (sum.y >= 0.f) ? sum.y : NEG_SLOPE * sum.y;
    sum.z = (sum.z >= 0.f) ? sum.z : NEG_SLOPE * sum.z;
    sum.w = (sum.w >= 0.f) ? sum.w : NEG_SLOPE * sum.w;
    ((float4*)out)[i4] = sum;
}

// ----------------------------------------------------------------
extern "C" void kernel_launch(void* const* d_in, const int* in_sizes, int n_in,
                              void* d_out, int out_size) {
    const float* x    = (const float*)d_in[0];
    const int*   gidx = (const int*)  d_in[1];
    const float* W    = (const float*)d_in[2];
    const float* bias = (const float*)d_in[3];
    const float* W3   = (const float*)d_in[4];
    const float* b3   = (const float*)d_in[5];
    float* out = (float*)d_out;

    {
        dim3 grid(D_DIM / 64, B_DIM / 64);
        transpose_split_kernel<<<grid, 256>>>(x);
    }
    {
        dim3 grid(B_DIM / 128, O_DIM / 128, N_DIM);   // (2,2,41)
        gemm1_kernel<<<grid, 256>>>(gidx, W, bias);
    }
    {
        dim3 grid(B_DIM / 128, E_DIM / 128, N_DIM);   // (2,4,41)
        gemm2_kernel<<<grid, 256>>>(W3);
    }
    {
        reduce_kernel<<<(B_DIM * E_DIM / 4) / 256, 256>>>(b3, out);
    }
}

// round 6
// speedup vs baseline: 2.4889x; 1.0005x over previous
#include <cuda_runtime.h>
#include <cuda_bf16.h>
#include <cstdint>

#define B_DIM 256
#define D_DIM 65536
#define N_DIM 41
#define G_DIM 2048
#define O_DIM 256
#define E_DIM 512
#define NO_DIM (N_DIM * O_DIM)   // 10496
#define NEG_SLOPE 0.2f

// Scratch (device globals, POD types only, total ~96.25 MB == proven round-2 level)
__device__ unsigned short g_xT_hi[(size_t)D_DIM * B_DIM];   // 32 MB
__device__ unsigned short g_xT_lo[(size_t)D_DIM * B_DIM];   // 32 MB
__device__ unsigned short g_H_hi[(size_t)B_DIM * NO_DIM];   // 5.4 MB
__device__ unsigned short g_H_lo[(size_t)B_DIM * NO_DIM];   // 5.4 MB
__device__ float g_P[(size_t)N_DIM * B_DIM * E_DIM];        // 21.5 MB

// ---------------------------------------------------------------- helpers
__device__ __forceinline__ uint32_t sptr(const void* p) {
    return (uint32_t)__cvta_generic_to_shared(p);
}
__device__ __forceinline__ void fsplit(float v, unsigned short& h, unsigned short& l) {
    __nv_bfloat16 bh = __float2bfloat16_rn(v);
    h = __bfloat16_as_ushort(bh);
    l = __bfloat16_as_ushort(__float2bfloat16_rn(v - __bfloat162float(bh)));
}
__device__ __forceinline__ void split_store8(float4 v, unsigned short* dhi, unsigned short* dlo) {
    unsigned short h0,h1,h2,h3,l0,l1,l2,l3;
    bsplitcall: ;
    fsplit(v.x,h0,l0); fsplit(v.y,h1,l1); fsplit(v.z,h2,l2); fsplit(v.w,h3,l3);
    *(uint2*)dhi = make_uint2((uint32_t)h0 | ((uint32_t)h1<<16), (uint32_t)h2 | ((uint32_t)h3<<16));
    *(uint2*)dlo = make_uint2((uint32_t)l0 | ((uint32_t)l1<<16), (uint32_t)l2 | ((uint32_t)l3<<16));
}
__device__ __forceinline__ void ldsm4t(uint32_t* r, uint32_t a) {
    asm volatile("ldmatrix.sync.aligned.m8n8.x4.trans.shared.b16 {%0,%1,%2,%3},[%4];"
                 : "=r"(r[0]), "=r"(r[1]), "=r"(r[2]), "=r"(r[3]) : "r"(a));
}
__device__ __forceinline__ void ldsm4(uint32_t* r, uint32_t a) {
    asm volatile("ldmatrix.sync.aligned.m8n8.x4.shared.b16 {%0,%1,%2,%3},[%4];"
                 : "=r"(r[0]), "=r"(r[1]), "=r"(r[2]), "=r"(r[3]) : "r"(a));
}
__device__ __forceinline__ void mma16816(float* c, const uint32_t* a, const uint32_t* b) {
    asm volatile("mma.sync.aligned.m16n8k16.row.col.f32.bf16.bf16.f32 "
                 "{%0,%1,%2,%3},{%4,%5,%6,%7},{%8,%9},{%0,%1,%2,%3};"
                 : "+f"(c[0]), "+f"(c[1]), "+f"(c[2]), "+f"(c[3])
                 : "r"(a[0]), "r"(a[1]), "r"(a[2]), "r"(a[3]), "r"(b[0]), "r"(b[1]));
}

// ---------------------------------------------------------------- transpose + split x
__global__ __launch_bounds__(256) void transpose_split_kernel(const float* __restrict__ x) {
    __shared__ float tile[64][65];
    int d0 = blockIdx.x * 64, b0 = blockIdx.y * 64;
    int t = threadIdx.x;
    int br = t / 16, dc = (t % 16) * 4;
#pragma unroll
    for (int p = 0; p < 4; p++) {
        int b = br + p * 16;
        float4 v = *(const float4*)&x[(size_t)(b0 + b) * D_DIM + d0 + dc];
        tile[b][dc] = v.x; tile[b][dc+1] = v.y; tile[b][dc+2] = v.z; tile[b][dc+3] = v.w;
    }
    __syncthreads();
    int dr = t / 16, bc = (t % 16) * 4;
#pragma unroll
    for (int p = 0; p < 4; p++) {
        int d = dr + p * 16;
        unsigned short h0,h1,h2,h3,l0,l1,l2,l3;
        fsplit(tile[bc][d],   h0, l0);
        fsplit(tile[bc+1][d], h1, l1);
        fsplit(tile[bc+2][d], h2, l2);
        fsplit(tile[bc+3][d], h3, l3);
        size_t off = (size_t)(d0 + d) * B_DIM + b0 + bc;
        *(uint2*)&g_xT_hi[off] = make_uint2((uint32_t)h0 | ((uint32_t)h1<<16),
                                            (uint32_t)h2 | ((uint32_t)h3<<16));
        *(uint2*)&g_xT_lo[off] = make_uint2((uint32_t)l0 | ((uint32_t)l1<<16),
                                            (uint32_t)l2 | ((uint32_t)l3<<16));
    }
}

// ---------------------------------------------------------------- GEMM1
// H[b][n*256+o] = sum_g xT[idx[n][g]][b] * W[n][g][o] + bias[n][o]
// A from pre-split bf16 xT (no conversion); B split from fp32 W in-kernel (round-2 path).
__global__ __launch_bounds__(256, 1) void gemm1_kernel(
    const int* __restrict__ gidx, const float* __restrict__ W, const float* __restrict__ bias)
{
    __shared__ int sIdx[G_DIM];                                   // 8 KB
    __shared__ alignas(16) unsigned short As[2][2][16][136];      // 17 KB
    __shared__ alignas(16) unsigned short Bs[2][2][16][136];      // 17 KB

    const int n     = blockIdx.z;
    const int bbase = blockIdx.x * 128;
    const int obase = blockIdx.y * 128;
    const int tid = threadIdx.x, lane = tid & 31, warp = tid >> 5;
    const int wm = (warp & 1) * 64, wn = (warp >> 1) * 32;

    // A loaders: 16 rows x 16 col-chunks of 8 bf16
    const int lrowA = tid >> 4;          // 0..15
    const int lcolA = (tid & 15) * 8;    // 0..120
    // B loaders (round-2 pattern): rows kk, kk+8; 4 fp32 cols each
    const int kkB  = tid >> 5;           // 0..7
    const int colB = (tid & 31) * 4;     // 0..124

    const int* grow = gidx + (size_t)n * G_DIM;
    for (int i = tid; i < G_DIM; i += 256) sIdx[i] = grow[i];
    __syncthreads();

    const float* Wn = W + (size_t)n * G_DIM * O_DIM;

    const int g8 = lane >> 3, i8 = lane & 7;
    const int a_krow = (g8 >> 1) * 8 + i8, a_mcol = (g8 & 1) * 8;
    const int b_krow = (g8 & 1) * 8 + i8, b_ncol = (g8 >> 1) * 8;

    float acc[4][4][4];
#pragma unroll
    for (int i = 0; i < 4; i++)
#pragma unroll
        for (int j = 0; j < 4; j++)
#pragma unroll
            for (int q = 0; q < 4; q++) acc[i][j][q] = 0.0f;

    uint4 ra_h, ra_l;
    float4 pb0, pb1;
    {
        int gi = sIdx[lrowA];
        ra_h = *(const uint4*)&g_xT_hi[(size_t)gi * B_DIM + bbase + lcolA];
        ra_l = *(const uint4*)&g_xT_lo[(size_t)gi * B_DIM + bbase + lcolA];
        pb0 = *(const float4*)&Wn[(size_t)kkB * O_DIM + obase + colB];
        pb1 = *(const float4*)&Wn[(size_t)(kkB + 8) * O_DIM + obase + colB];
    }
    int buf = 0;
    *(uint4*)&As[buf][0][lrowA][lcolA] = ra_h;
    *(uint4*)&As[buf][1][lrowA][lcolA] = ra_l;
    split_store8(pb0, &Bs[buf][0][kkB][colB],   &Bs[buf][1][kkB][colB]);
    split_store8(pb1, &Bs[buf][0][kkB+8][colB], &Bs[buf][1][kkB+8][colB]);
    __syncthreads();

    const int NCHUNK = G_DIM / 16;  // 128
    for (int ch = 0; ch < NCHUNK; ch++) {
        if (ch + 1 < NCHUNK) {
            int k0 = (ch + 1) * 16;
            int gi = sIdx[k0 + lrowA];
            ra_h = *(const uint4*)&g_xT_hi[(size_t)gi * B_DIM + bbase + lcolA];
            ra_l = *(const uint4*)&g_xT_lo[(size_t)gi * B_DIM + bbase + lcolA];
            pb0 = *(const float4*)&Wn[(size_t)(k0 + kkB) * O_DIM + obase + colB];
            pb1 = *(const float4*)&Wn[(size_t)(k0 + kkB + 8) * O_DIM + obase + colB];
        }
        uint32_t af[2][4][4], bfv[2][2][4];
#pragma unroll
        for (int v = 0; v < 2; v++)
#pragma unroll
            for (int mt = 0; mt < 4; mt++)
                ldsm4t(af[v][mt], sptr(&As[buf][v][a_krow][wm + mt * 16 + a_mcol]));
#pragma unroll
        for (int v = 0; v < 2; v++)
#pragma unroll
            for (int np = 0; np < 2; np++)
                ldsm4t(bfv[v][np], sptr(&Bs[buf][v][b_krow][wn + np * 16 + b_ncol]));
#pragma unroll
        for (int mt = 0; mt < 4; mt++)
#pragma unroll
            for (int nt = 0; nt < 4; nt++) {
                const uint32_t* bh = &bfv[0][nt >> 1][(nt & 1) * 2];
                const uint32_t* bl = &bfv[1][nt >> 1][(nt & 1) * 2];
                mma16816(acc[mt][nt], af[0][mt], bh);
                mma16816(acc[mt][nt], af[0][mt], bl);
                mma16816(acc[mt][nt], af[1][mt], bh);
            }
        if (ch + 1 < NCHUNK) {
            buf ^= 1;
            *(uint4*)&As[buf][0][lrowA][lcolA] = ra_h;
            *(uint4*)&As[buf][1][lrowA][lcolA] = ra_l;
            split_store8(pb0, &Bs[buf][0][kkB][colB],   &Bs[buf][1][kkB][colB]);
            split_store8(pb1, &Bs[buf][0][kkB+8][colB], &Bs[buf][1][kkB+8][colB]);
            __syncthreads();
        }
    }

    // epilogue: H -> (hi,lo) bf16, row-major [B][NO]
    const int r = lane >> 2, c = (lane & 3) * 2;
#pragma unroll
    for (int mt = 0; mt < 4; mt++) {
#pragma unroll
        for (int nt = 0; nt < 4; nt++) {
            int ocol = obase + wn + nt * 8 + c;
            float bv0 = bias[n * O_DIM + ocol];
            float bv1 = bias[n * O_DIM + ocol + 1];
            int b0 = bbase + wm + mt * 16 + r;
#pragma unroll
            for (int q = 0; q < 2; q++) {
                float h0 = acc[mt][nt][q*2]   + bv0;
                float h1 = acc[mt][nt][q*2+1] + bv1;
                unsigned short hh0, hl0, hh1, hl1;
                fsplit(h0, hh0, hl0);
                fsplit(h1, hh1, hl1);
                size_t base = (size_t)(b0 + q*8) * NO_DIM + (size_t)n * O_DIM + ocol;
                *(uint32_t*)&g_H_hi[base] = (uint32_t)hh0 | ((uint32_t)hh1 << 16);
                *(uint32_t*)&g_H_lo[base] = (uint32_t)hl0 | ((uint32_t)hl1 << 16);
            }
        }
    }
}

// ---------------------------------------------------------------- GEMM2 split-K
// P[s][b][e] = sum_{k in split s} H[b][k] * W3[k][e]
// A from pre-split bf16 H; B split from fp32 W3 in-kernel (round-2 path).
__global__ __launch_bounds__(256, 1) void gemm2_kernel(const float* __restrict__ W3)
{
    __shared__ alignas(16) unsigned short As[2][2][128][24];   // 24 KB  [m][k]
    __shared__ alignas(16) unsigned short Bs[2][2][16][136];   // 17 KB  [k][e]

    const int s     = blockIdx.z;
    const int bbase = blockIdx.x * 128;
    const int ebase = blockIdx.y * 128;
    const int tid = threadIdx.x, lane = tid & 31, warp = tid >> 5;
    const int wm = (warp & 1) * 64, wn = (warp >> 1) * 32;

    const int arow = tid >> 1, ahalf = (tid & 1) * 8;   // A: 128 rows x 2 chunks of 8
    const int kkB  = tid >> 5, colB = (tid & 31) * 4;   // B: round-2 pattern

    const int g8 = lane >> 3, i8 = lane & 7;
    const int a_mrow = (g8 & 1) * 8 + i8, a_kcol = (g8 >> 1) * 8;
    const int b_krow = (g8 & 1) * 8 + i8, b_ncol = (g8 >> 1) * 8;

    float acc[4][4][4];
#pragma unroll
    for (int i = 0; i < 4; i++)
#pragma unroll
        for (int j = 0; j < 4; j++)
#pragma unroll
            for (int q = 0; q < 4; q++) acc[i][j][q] = 0.0f;

    const int kbeg = s * 256;
    uint4 ra_h, ra_l;
    float4 pb0, pb1;
    {
        ra_h = *(const uint4*)&g_H_hi[(size_t)(bbase + arow) * NO_DIM + kbeg + ahalf];
        ra_l = *(const uint4*)&g_H_lo[(size_t)(bbase + arow) * NO_DIM + kbeg + ahalf];
        pb0 = *(const float4*)&W3[(size_t)(kbeg + kkB) * E_DIM + ebase + colB];
        pb1 = *(const float4*)&W3[(size_t)(kbeg + kkB + 8) * E_DIM + ebase + colB];
    }
    int buf = 0;
    *(uint4*)&As[buf][0][arow][ahalf] = ra_h;
    *(uint4*)&As[buf][1][arow][ahalf] = ra_l;
    split_store8(pb0, &Bs[buf][0][kkB][colB],   &Bs[buf][1][kkB][colB]);
    split_store8(pb1, &Bs[buf][0][kkB+8][colB], &Bs[buf][1][kkB+8][colB]);
    __syncthreads();

    const int NCHUNK = 16;
    for (int ch = 0; ch < NCHUNK; ch++) {
        if (ch + 1 < NCHUNK) {
            int k0 = kbeg + (ch + 1) * 16;
            ra_h = *(const uint4*)&g_H_hi[(size_t)(bbase + arow) * NO_DIM + k0 + ahalf];
            ra_l = *(const uint4*)&g_H_lo[(size_t)(bbase + arow) * NO_DIM + k0 + ahalf];
            pb0 = *(const float4*)&W3[(size_t)(k0 + kkB) * E_DIM + ebase + colB];
            pb1 = *(const float4*)&W3[(size_t)(k0 + kkB + 8) * E_DIM + ebase + colB];
        }
        uint32_t af[2][4][4], bfv[2][2][4];
#pragma unroll
        for (int v = 0; v < 2; v++)
#pragma unroll
            for (int mt = 0; mt < 4; mt++)
                ldsm4(af[v][mt], sptr(&As[buf][v][wm + mt * 16 + a_mrow][a_kcol]));
#pragma unroll
        for (int v = 0; v < 2; v++)
#pragma unroll
            for (int np = 0; np < 2; np++)
                ldsm4t(bfv[v][np], sptr(&Bs[buf][v][b_krow][wn + np * 16 + b_ncol]));
#pragma unroll
        for (int mt = 0; mt < 4; mt++)
#pragma unroll
            for (int nt = 0; nt < 4; nt++) {
                const uint32_t* bh = &bfv[0][nt >> 1][(nt & 1) * 2];
                const uint32_t* bl = &bfv[1][nt >> 1][(nt & 1) * 2];
                mma16816(acc[mt][nt], af[0][mt], bh);
                mma16816(acc[mt][nt], af[0][mt], bl);
                mma16816(acc[mt][nt], af[1][mt], bh);
            }
        if (ch + 1 < NCHUNK) {
            buf ^= 1;
            *(uint4*)&As[buf][0][arow][ahalf] = ra_h;
            *(uint4*)&As[buf][1][arow][ahalf] = ra_l;
            split_store8(pb0, &Bs[buf][0][kkB][colB],   &Bs[buf][1][kkB][colB]);
            split_store8(pb1, &Bs[buf][0][kkB+8][colB], &Bs[buf][1][kkB+8][colB]);
            __syncthreads();
        }
    }

    float* Ps = g_P + (size_t)s * B_DIM * E_DIM;
    const int r = lane >> 2, c = (lane & 3) * 2;
#pragma unroll
    for (int mt = 0; mt < 4; mt++) {
#pragma unroll
        for (int nt = 0; nt < 4; nt++) {
            int ecol = ebase + wn + nt * 8 + c;
            int b0 = bbase + wm + mt * 16 + r;
            *(float2*)&Ps[(size_t)b0 * E_DIM + ecol] =
                make_float2(acc[mt][nt][0], acc[mt][nt][1]);
            *(float2*)&Ps[(size_t)(b0 + 8) * E_DIM + ecol] =
                make_float2(acc[mt][nt][2], acc[mt][nt][3]);
        }
    }
}

// ---------------------------------------------------------------- reduce
__global__ __launch_bounds__(256) void reduce_kernel(const float* __restrict__ b3, float* __restrict__ out) {
    int i4 = blockIdx.x * 256 + threadIdx.x;
    int e4 = i4 & (E_DIM / 4 - 1);
    float4 sum = ((const float4*)b3)[e4];
#pragma unroll
    for (int s = 0; s < N_DIM; s++) {
        float4 p = ((const float4*)g_P)[(size_t)s * (B_DIM * E_DIM / 4) + i4];
        sum.x += p.x; sum.y += p.y; sum.z += p.z; sum.w += p.w;
    }
    sum.x = (sum.x >= 0.f) ? sum.x : NEG_SLOPE * sum.x;
    sum.y = (sum.y >= 0.f) ? sum.y : NEG_SLOPE * sum.y;
    sum.z = (sum.z >= 0.f) ? sum.z : NEG_SLOPE * sum.z;
    sum.w = (sum.w >= 0.f) ? sum.w : NEG_SLOPE * sum.w;
    ((float4*)out)[i4] = sum;
}

// ----------------------------------------------------------------
extern "C" void kernel_launch(void* const* d_in, const int* in_sizes, int n_in,
                              void* d_out, int out_size) {
    const float* x    = (const float*)d_in[0];
    const int*   gidx = (const int*)  d_in[1];
    const float* W    = (const float*)d_in[2];
    const float* bias = (const float*)d_in[3];
    const float* W3   = (const float*)d_in[4];
    const float* b3   = (const float*)d_in[5];
    float* out = (float*)d_out;

    {
        dim3 grid(D_DIM / 64, B_DIM / 64);
        transpose_split_kernel<<<grid, 256>>>(x);
    }
    {
        dim3 grid(B_DIM / 128, O_DIM / 128, N_DIM);   // (2,2,41)
        gemm1_kernel<<<grid, 256>>>(gidx, W, bias);
    }
    {
        dim3 grid(B_DIM / 128, E_DIM / 128, N_DIM);   // (2,4,41)
        gemm2_kernel<<<grid, 256>>>(W3);
    }
    {
        reduce_kernel<<<(B_DIM * E_DIM / 4) / 256, 256>>>(b3, out);
    }
}

// round 8
// speedup vs baseline: 2.7516x; 1.1056x over previous
#include <cuda_runtime.h>
#include <cuda_bf16.h>
#include <cstdint>

#define B_DIM 256
#define D_DIM 65536
#define N_DIM 41
#define G_DIM 2048
#define O_DIM 256
#define E_DIM 512
#define NO_DIM (N_DIM * O_DIM)
#define NEG_SLOPE 0.2f

// statics: 96.25 MB (proven level)
__device__ unsigned short g_xT_hi[(size_t)D_DIM * B_DIM];
__device__ unsigned short g_xT_lo[(size_t)D_DIM * B_DIM];
__device__ unsigned short g_H_hi[(size_t)B_DIM * NO_DIM];
__device__ unsigned short g_H_lo[(size_t)B_DIM * NO_DIM];
__device__ float g_P[(size_t)N_DIM * B_DIM * E_DIM];

// ---------------------------------------------------------------- helpers
__device__ __forceinline__ uint32_t sptr(const void* p) {
    return (uint32_t)__cvta_generic_to_shared(p);
}
__device__ __forceinline__ void fsplit(float v, unsigned short& h, unsigned short& l) {
    __nv_bfloat16 bh = __float2bfloat16_rn(v);
    h = __bfloat16_as_ushort(bh);
    l = __bfloat16_as_ushort(__float2bfloat16_rn(v - __bfloat162float(bh)));
}
__device__ __forceinline__ void split_store8(float4 v, unsigned short* dhi, unsigned short* dlo) {
    unsigned short h0,h1,h2,h3,l0,l1,l2,l3;
    fsplit(v.x,h0,l0); fsplit(v.y,h1,l1); fsplit(v.z,h2,l2); fsplit(v.w,h3,l3);
    *(uint2*)dhi = make_uint2((uint32_t)h0|((uint32_t)h1<<16), (uint32_t)h2|((uint32_t)h3<<16));
    *(uint2*)dlo = make_uint2((uint32_t)l0|((uint32_t)l1<<16), (uint32_t)l2|((uint32_t)l3<<16));
}
__device__ __forceinline__ void ldsm4t(uint32_t* r, uint32_t a) {
    asm volatile("ldmatrix.sync.aligned.m8n8.x4.trans.shared.b16 {%0,%1,%2,%3},[%4];"
                 : "=r"(r[0]), "=r"(r[1]), "=r"(r[2]), "=r"(r[3]) : "r"(a));
}
__device__ __forceinline__ void ldsm4(uint32_t* r, uint32_t a) {
    asm volatile("ldmatrix.sync.aligned.m8n8.x4.shared.b16 {%0,%1,%2,%3},[%4];"
                 : "=r"(r[0]), "=r"(r[1]), "=r"(r[2]), "=r"(r[3]) : "r"(a));
}
__device__ __forceinline__ void mma16816(float* c, const uint32_t* a, const uint32_t* b) {
    asm volatile("mma.sync.aligned.m16n8k16.row.col.f32.bf16.bf16.f32 "
                 "{%0,%1,%2,%3},{%4,%5,%6,%7},{%8,%9},{%0,%1,%2,%3};"
                 : "+f"(c[0]), "+f"(c[1]), "+f"(c[2]), "+f"(c[3])
                 : "r"(a[0]), "r"(a[1]), "r"(a[2]), "r"(a[3]), "r"(b[0]), "r"(b[1]));
}

// ---------------------------------------------------------------- transpose + split x
__global__ __launch_bounds__(256) void transpose_split_kernel(const float* __restrict__ x) {
    __shared__ float tile[64][65];
    int d0 = blockIdx.x * 64, b0 = blockIdx.y * 64;
    int t = threadIdx.x;
    int br = t / 16, dc = (t % 16) * 4;
#pragma unroll
    for (int p = 0; p < 4; p++) {
        int b = br + p * 16;
        float4 v = *(const float4*)&x[(size_t)(b0 + b) * D_DIM + d0 + dc];
        tile[b][dc] = v.x; tile[b][dc+1] = v.y; tile[b][dc+2] = v.z; tile[b][dc+3] = v.w;
    }
    __syncthreads();
    int dr = t / 16, bc = (t % 16) * 4;
#pragma unroll
    for (int p = 0; p < 4; p++) {
        int d = dr + p * 16;
        unsigned short h0,h1,h2,h3,l0,l1,l2,l3;
        fsplit(tile[bc][d], h0, l0);   fsplit(tile[bc+1][d], h1, l1);
        fsplit(tile[bc+2][d], h2, l2); fsplit(tile[bc+3][d], h3, l3);
        size_t off = (size_t)(d0 + d) * B_DIM + b0 + bc;
        *(uint2*)&g_xT_hi[off] = make_uint2((uint32_t)h0|((uint32_t)h1<<16), (uint32_t)h2|((uint32_t)h3<<16));
        *(uint2*)&g_xT_lo[off] = make_uint2((uint32_t)l0|((uint32_t)l1<<16), (uint32_t)l2|((uint32_t)l3<<16));
    }
}

// ---------------------------------------------------------------- GEMM1 (HMMA, prefetch distance 2)
// H[b][n*256+o] = sum_g xT[idx[n][g]][b] * W[n][g][o] + bias[n][o]
__global__ __launch_bounds__(256, 1) void gemm1_kernel(
    const int* __restrict__ gidx, const float* __restrict__ W, const float* __restrict__ bias)
{
    __shared__ unsigned short sIdx[G_DIM];                        // 4 KB
    __shared__ alignas(16) unsigned short As[2][2][16][136];      // 17 KB
    __shared__ alignas(16) unsigned short Bs[2][2][16][136];      // 17 KB

    const int n     = blockIdx.z;
    const int bbase = blockIdx.x * 128;
    const int obase = blockIdx.y * 128;
    const int tid = threadIdx.x, lane = tid & 31, warp = tid >> 5;
    const int wm = (warp & 1) * 64, wn = (warp >> 1) * 32;
    const int lrowA = tid >> 4, lcolA = (tid & 15) * 8;
    const int kkB = tid >> 5, colB = (tid & 31) * 4;

    for (int i = tid; i < G_DIM; i += 256)
        sIdx[i] = (unsigned short)gidx[(size_t)n * G_DIM + i];
    __syncthreads();

    const float* Wn = W + (size_t)n * G_DIM * O_DIM;
    const int g8 = lane >> 3, i8 = lane & 7;
    const int a_krow = (g8 >> 1) * 8 + i8, a_mcol = (g8 & 1) * 8;
    const int b_krow = (g8 & 1) * 8 + i8, b_ncol = (g8 >> 1) * 8;

    float acc[4][4][4];
#pragma unroll
    for (int i = 0; i < 4; i++)
#pragma unroll
        for (int j = 0; j < 4; j++)
#pragma unroll
            for (int q = 0; q < 4; q++) acc[i][j][q] = 0.0f;

    // ---- pipeline lambdas ----
    auto ldg = [&](int ch, uint4& ah, uint4& al, float4& p0, float4& p1) {
        int k0 = ch * 16;
        int gi = sIdx[k0 + lrowA];
        ah = *(const uint4*)&g_xT_hi[(size_t)gi * B_DIM + bbase + lcolA];
        al = *(const uint4*)&g_xT_lo[(size_t)gi * B_DIM + bbase + lcolA];
        p0 = *(const float4*)&Wn[(size_t)(k0 + kkB) * O_DIM + obase + colB];
        p1 = *(const float4*)&Wn[(size_t)(k0 + kkB + 8) * O_DIM + obase + colB];
    };
    auto sts = [&](int buf, uint4 ah, uint4 al, float4 p0, float4 p1) {
        *(uint4*)&As[buf][0][lrowA][lcolA] = ah;
        *(uint4*)&As[buf][1][lrowA][lcolA] = al;
        split_store8(p0, &Bs[buf][0][kkB][colB],   &Bs[buf][1][kkB][colB]);
        split_store8(p1, &Bs[buf][0][kkB+8][colB], &Bs[buf][1][kkB+8][colB]);
    };
    auto compute = [&](int buf) {
        uint32_t af[2][4][4], bfv[2][2][4];
#pragma unroll
        for (int v = 0; v < 2; v++)
#pragma unroll
            for (int mt = 0; mt < 4; mt++)
                ldsm4t(af[v][mt], sptr(&As[buf][v][a_krow][wm + mt * 16 + a_mcol]));
#pragma unroll
        for (int v = 0; v < 2; v++)
#pragma unroll
            for (int np = 0; np < 2; np++)
                ldsm4t(bfv[v][np], sptr(&Bs[buf][v][b_krow][wn + np * 16 + b_ncol]));
#pragma unroll
        for (int mt = 0; mt < 4; mt++)
#pragma unroll
            for (int nt = 0; nt < 4; nt++) {
                const uint32_t* bh = &bfv[0][nt >> 1][(nt & 1) * 2];
                const uint32_t* bl = &bfv[1][nt >> 1][(nt & 1) * 2];
                mma16816(acc[mt][nt], af[0][mt], bh);
                mma16816(acc[mt][nt], af[0][mt], bl);
                mma16816(acc[mt][nt], af[1][mt], bh);
            }
    };

    // ---- prologue: smem0 = ch0, regset A = ch1 ----
    uint4 Ah0, Al0, Ah1, Al1;
    float4 B00, B01, B10, B11;
    ldg(0, Ah0, Al0, B00, B01);
    sts(0, Ah0, Al0, B00, B01);
    ldg(1, Ah0, Al0, B00, B01);
    __syncthreads();

    const int NCHUNK = G_DIM / 16;  // 128 (even)
    for (int ch = 0; ch < NCHUNK; ch += 2) {
        if (ch + 2 < NCHUNK) ldg(ch + 2, Ah1, Al1, B10, B11);
        compute(0);
        sts(1, Ah0, Al0, B00, B01);          // ch+1 data
        __syncthreads();
        if (ch + 3 < NCHUNK) ldg(ch + 3, Ah0, Al0, B00, B01);
        compute(1);
        if (ch + 2 < NCHUNK) sts(0, Ah1, Al1, B10, B11);   // ch+2 data
        __syncthreads();
    }

    // epilogue: H -> (hi,lo) bf16, row-major [B][NO]
    const int r = lane >> 2, c = (lane & 3) * 2;
#pragma unroll
    for (int mt = 0; mt < 4; mt++)
#pragma unroll
        for (int nt = 0; nt < 4; nt++) {
            int ocol = obase + wn + nt * 8 + c;
            float bv0 = bias[n * O_DIM + ocol], bv1 = bias[n * O_DIM + ocol + 1];
            int b0 = bbase + wm + mt * 16 + r;
#pragma unroll
            for (int q = 0; q < 2; q++) {
                float h0 = acc[mt][nt][q*2] + bv0, h1 = acc[mt][nt][q*2+1] + bv1;
                unsigned short hh0, hl0, hh1, hl1;
                fsplit(h0, hh0, hl0); fsplit(h1, hh1, hl1);
                size_t base = (size_t)(b0 + q*8) * NO_DIM + (size_t)n * O_DIM + ocol;
                *(uint32_t*)&g_H_hi[base] = (uint32_t)hh0 | ((uint32_t)hh1 << 16);
                *(uint32_t*)&g_H_lo[base] = (uint32_t)hl0 | ((uint32_t)hl1 << 16);
            }
        }
}

// ---------------------------------------------------------------- GEMM2 split-K (prefetch distance 2)
__global__ __launch_bounds__(256, 1) void gemm2_kernel(const float* __restrict__ W3)
{
    __shared__ alignas(16) unsigned short As[2][2][128][24];   // 24 KB
    __shared__ alignas(16) unsigned short Bs[2][2][16][136];   // 17 KB

    const int s = blockIdx.z, bbase = blockIdx.x * 128, ebase = blockIdx.y * 128;
    const int tid = threadIdx.x, lane = tid & 31, warp = tid >> 5;
    const int wm = (warp & 1) * 64, wn = (warp >> 1) * 32;
    const int arow = tid >> 1, ahalf = (tid & 1) * 8;
    const int kkB = tid >> 5, colB = (tid & 31) * 4;
    const int g8 = lane >> 3, i8 = lane & 7;
    const int a_mrow = (g8 & 1) * 8 + i8, a_kcol = (g8 >> 1) * 8;
    const int b_krow = (g8 & 1) * 8 + i8, b_ncol = (g8 >> 1) * 8;

    float acc[4][4][4];
#pragma unroll
    for (int i = 0; i < 4; i++)
#pragma unroll
        for (int j = 0; j < 4; j++)
#pragma unroll
            for (int q = 0; q < 4; q++) acc[i][j][q] = 0.0f;

    const int kbeg = s * 256;

    auto ldg = [&](int ch, uint4& ah, uint4& al, float4& p0, float4& p1) {
        int k0 = kbeg + ch * 16;
        ah = *(const uint4*)&g_H_hi[(size_t)(bbase + arow) * NO_DIM + k0 + ahalf];
        al = *(const uint4*)&g_H_lo[(size_t)(bbase + arow) * NO_DIM + k0 + ahalf];
        p0 = *(const float4*)&W3[(size_t)(k0 + kkB) * E_DIM + ebase + colB];
        p1 = *(const float4*)&W3[(size_t)(k0 + kkB + 8) * E_DIM + ebase + colB];
    };
    auto sts = [&](int buf, uint4 ah, uint4 al, float4 p0, float4 p1) {
        *(uint4*)&As[buf][0][arow][ahalf] = ah;
        *(uint4*)&As[buf][1][arow][ahalf] = al;
        split_store8(p0, &Bs[buf][0][kkB][colB],   &Bs[buf][1][kkB][colB]);
        split_store8(p1, &Bs[buf][0][kkB+8][colB], &Bs[buf][1][kkB+8][colB]);
    };
    auto compute = [&](int buf) {
        uint32_t af[2][4][4], bfv[2][2][4];
#pragma unroll
        for (int v = 0; v < 2; v++)
#pragma unroll
            for (int mt = 0; mt < 4; mt++)
                ldsm4(af[v][mt], sptr(&As[buf][v][wm + mt * 16 + a_mrow][a_kcol]));
#pragma unroll
        for (int v = 0; v < 2; v++)
#pragma unroll
            for (int np = 0; np < 2; np++)
                ldsm4t(bfv[v][np], sptr(&Bs[buf][v][b_krow][wn + np * 16 + b_ncol]));
#pragma unroll
        for (int mt = 0; mt < 4; mt++)
#pragma unroll
            for (int nt = 0; nt < 4; nt++) {
                const uint32_t* bh = &bfv[0][nt >> 1][(nt & 1) * 2];
                const uint32_t* bl = &bfv[1][nt >> 1][(nt & 1) * 2];
                mma16816(acc[mt][nt], af[0][mt], bh);
                mma16816(acc[mt][nt], af[0][mt], bl);
                mma16816(acc[mt][nt], af[1][mt], bh);
            }
    };

    uint4 Ah0, Al0, Ah1, Al1;
    float4 B00, B01, B10, B11;
    ldg(0, Ah0, Al0, B00, B01);
    sts(0, Ah0, Al0, B00, B01);
    ldg(1, Ah0, Al0, B00, B01);
    __syncthreads();

    const int NCHUNK = 16;  // even
    for (int ch = 0; ch < NCHUNK; ch += 2) {
        if (ch + 2 < NCHUNK) ldg(ch + 2, Ah1, Al1, B10, B11);
        compute(0);
        sts(1, Ah0, Al0, B00, B01);
        __syncthreads();
        if (ch + 3 < NCHUNK) ldg(ch + 3, Ah0, Al0, B00, B01);
        compute(1);
        if (ch + 2 < NCHUNK) sts(0, Ah1, Al1, B10, B11);
        __syncthreads();
    }

    float* Ps = g_P + (size_t)s * B_DIM * E_DIM;
    const int r = lane >> 2, c = (lane & 3) * 2;
#pragma unroll
    for (int mt = 0; mt < 4; mt++)
#pragma unroll
        for (int nt = 0; nt < 4; nt++) {
            int ecol = ebase + wn + nt * 8 + c;
            int b0 = bbase + wm + mt * 16 + r;
            *(float2*)&Ps[(size_t)b0 * E_DIM + ecol] = make_float2(acc[mt][nt][0], acc[mt][nt][1]);
            *(float2*)&Ps[(size_t)(b0 + 8) * E_DIM + ecol] = make_float2(acc[mt][nt][2], acc[mt][nt][3]);
        }
}

// ---------------------------------------------------------------- reduce
__global__ __launch_bounds__(256) void reduce_kernel(const float* __restrict__ b3, float* __restrict__ out) {
    int i4 = blockIdx.x * 256 + threadIdx.x;
    int e4 = i4 & (E_DIM / 4 - 1);
    float4 sum = ((const float4*)b3)[e4];
#pragma unroll
    for (int s = 0; s < N_DIM; s++) {
        float4 p = ((const float4*)g_P)[(size_t)s * (B_DIM * E_DIM / 4) + i4];
        sum.x += p.x; sum.y += p.y; sum.z += p.z; sum.w += p.w;
    }
    sum.x = (sum.x >= 0.f) ? sum.x : NEG_SLOPE * sum.x;
    sum.y = (sum.y >= 0.f) ? sum.y : NEG_SLOPE * sum.y;
    sum.z = (sum.z >= 0.f) ? sum.z : NEG_SLOPE * sum.z;
    sum.w = (sum.w >= 0.f) ? sum.w : NEG_SLOPE * sum.w;
    ((float4*)out)[i4] = sum;
}

// ----------------------------------------------------------------
extern "C" void kernel_launch(void* const* d_in, const int* in_sizes, int n_in,
                              void* d_out, int out_size) {
    const float* x    = (const float*)d_in[0];
    const int*   gidx = (const int*)  d_in[1];
    const float* W    = (const float*)d_in[2];
    const float* bias = (const float*)d_in[3];
    const float* W3   = (const float*)d_in[4];
    const float* b3   = (const float*)d_in[5];
    float* out = (float*)d_out;

    {
        dim3 grid(D_DIM / 64, B_DIM / 64);
        transpose_split_kernel<<<grid, 256>>>(x);
    }
    {
        dim3 grid(B_DIM / 128, O_DIM / 128, N_DIM);   // (2,2,41)
        gemm1_kernel<<<grid, 256>>>(gidx, W, bias);
    }
    {
        dim3 grid(B_DIM / 128, E_DIM / 128, N_DIM);   // (2,4,41)
        gemm2_kernel<<<grid, 256>>>(W3);
    }
    {
        reduce_kernel<<<(B_DIM * E_DIM / 4) / 256, 256>>>(b3, out);
    }
}

// round 9
// speedup vs baseline: 3.7221x; 1.3527x over previous
#include <cuda_runtime.h>
#include <cuda_bf16.h>
#include <cuda_fp16.h>
#include <cstdint>

#define B_DIM 256
#define D_DIM 65536
#define N_DIM 41
#define G_DIM 2048
#define O_DIM 256
#define E_DIM 512
#define NO_DIM (N_DIM * O_DIM)
#define NEG_SLOPE 0.2f

// statics: 96.25 MB (proven level). xT holds fp16 bits now; H holds bf16 bits.
__device__ unsigned short g_xT_hi[(size_t)D_DIM * B_DIM];
__device__ unsigned short g_xT_lo[(size_t)D_DIM * B_DIM];
__device__ unsigned short g_H_hi[(size_t)B_DIM * NO_DIM];
__device__ unsigned short g_H_lo[(size_t)B_DIM * NO_DIM];
__device__ float g_P[(size_t)N_DIM * B_DIM * E_DIM];

// ---------------------------------------------------------------- helpers
__device__ __forceinline__ uint32_t sptr(const void* p) {
    return (uint32_t)__cvta_generic_to_shared(p);
}
// bf16 split (for H / gemm2 path)
__device__ __forceinline__ void fsplit(float v, unsigned short& h, unsigned short& l) {
    __nv_bfloat16 bh = __float2bfloat16_rn(v);
    h = __bfloat16_as_ushort(bh);
    l = __bfloat16_as_ushort(__float2bfloat16_rn(v - __bfloat162float(bh)));
}
// fp16 split (for x / gemm1 path)
__device__ __forceinline__ void hsplit(float v, unsigned short& h, unsigned short& l) {
    __half hh = __float2half_rn(v);
    h = __half_as_ushort(hh);
    l = __half_as_ushort(__float2half_rn(v - __half2float(hh)));
}
__device__ __forceinline__ void split_store8(float4 v, unsigned short* dhi, unsigned short* dlo) {
    unsigned short h0,h1,h2,h3,l0,l1,l2,l3;
    fsplit(v.x,h0,l0); fsplit(v.y,h1,l1); fsplit(v.z,h2,l2); fsplit(v.w,h3,l3);
    *(uint2*)dhi = make_uint2((uint32_t)h0|((uint32_t)h1<<16), (uint32_t)h2|((uint32_t)h3<<16));
    *(uint2*)dlo = make_uint2((uint32_t)l0|((uint32_t)l1<<16), (uint32_t)l2|((uint32_t)l3<<16));
}
__device__ __forceinline__ void ldsm4t(uint32_t* r, uint32_t a) {
    asm volatile("ldmatrix.sync.aligned.m8n8.x4.trans.shared.b16 {%0,%1,%2,%3},[%4];"
                 : "=r"(r[0]), "=r"(r[1]), "=r"(r[2]), "=r"(r[3]) : "r"(a));
}
__device__ __forceinline__ void ldsm4(uint32_t* r, uint32_t a) {
    asm volatile("ldmatrix.sync.aligned.m8n8.x4.shared.b16 {%0,%1,%2,%3},[%4];"
                 : "=r"(r[0]), "=r"(r[1]), "=r"(r[2]), "=r"(r[3]) : "r"(a));
}
// bf16 MMA (gemm2)
__device__ __forceinline__ void mma16816(float* c, const uint32_t* a, const uint32_t* b) {
    asm volatile("mma.sync.aligned.m16n8k16.row.col.f32.bf16.bf16.f32 "
                 "{%0,%1,%2,%3},{%4,%5,%6,%7},{%8,%9},{%0,%1,%2,%3};"
                 : "+f"(c[0]), "+f"(c[1]), "+f"(c[2]), "+f"(c[3])
                 : "r"(a[0]), "r"(a[1]), "r"(a[2]), "r"(a[3]), "r"(b[0]), "r"(b[1]));
}
// fp16 MMA (gemm1)
__device__ __forceinline__ void mma16816h(float* c, const uint32_t* a, const uint32_t* b) {
    asm volatile("mma.sync.aligned.m16n8k16.row.col.f32.f16.f16.f32 "
                 "{%0,%1,%2,%3},{%4,%5,%6,%7},{%8,%9},{%0,%1,%2,%3};"
                 : "+f"(c[0]), "+f"(c[1]), "+f"(c[2]), "+f"(c[3])
                 : "r"(a[0]), "r"(a[1]), "r"(a[2]), "r"(a[3]), "r"(b[0]), "r"(b[1]));
}

// ---------------------------------------------------------------- transpose + fp16-split x
__global__ __launch_bounds__(256) void transpose_split_kernel(const float* __restrict__ x) {
    __shared__ float tile[64][65];
    int d0 = blockIdx.x * 64, b0 = blockIdx.y * 64;
    int t = threadIdx.x;
    int br = t / 16, dc = (t % 16) * 4;
#pragma unroll
    for (int p = 0; p < 4; p++) {
        int b = br + p * 16;
        float4 v = *(const float4*)&x[(size_t)(b0 + b) * D_DIM + d0 + dc];
        tile[b][dc] = v.x; tile[b][dc+1] = v.y; tile[b][dc+2] = v.z; tile[b][dc+3] = v.w;
    }
    __syncthreads();
    int dr = t / 16, bc = (t % 16) * 4;
#pragma unroll
    for (int p = 0; p < 4; p++) {
        int d = dr + p * 16;
        unsigned short h0,h1,h2,h3,l0,l1,l2,l3;
        hsplit(tile[bc][d], h0, l0);   hsplit(tile[bc+1][d], h1, l1);
        hsplit(tile[bc+2][d], h2, l2); hsplit(tile[bc+3][d], h3, l3);
        size_t off = (size_t)(d0 + d) * B_DIM + b0 + bc;
        *(uint2*)&g_xT_hi[off] = make_uint2((uint32_t)h0|((uint32_t)h1<<16), (uint32_t)h2|((uint32_t)h3<<16));
        *(uint2*)&g_xT_lo[off] = make_uint2((uint32_t)l0|((uint32_t)l1<<16), (uint32_t)l2|((uint32_t)l3<<16));
    }
}

// ---------------------------------------------------------------- GEMM1 (fp16 2-term, tile 128x64, prefetch-2)
// H[b][n*256+o] = sum_g x[b][idx] * W[n][g][o] + bias; A = (xh+xl) fp16, B = fp16(W)
__global__ __launch_bounds__(256, 1) void gemm1_kernel(
    const int* __restrict__ gidx, const float* __restrict__ W, const float* __restrict__ bias)
{
    __shared__ unsigned short sIdx[G_DIM];                        // 4 KB
    __shared__ alignas(16) unsigned short As[2][2][16][136];      // 17 KB
    __shared__ alignas(16) unsigned short Bs[2][16][72];          // 4.5 KB

    const int n     = blockIdx.z;
    const int bbase = blockIdx.x * 128;
    const int obase = blockIdx.y * 64;
    const int tid = threadIdx.x, lane = tid & 31, warp = tid >> 5;
    const int wm = (warp & 1) * 64, wn = (warp >> 1) * 16;
    const int lrowA = tid >> 4, lcolA = (tid & 15) * 8;
    const int kkB = tid >> 4, colB = (tid & 15) * 4;

    for (int i = tid; i < G_DIM; i += 256)
        sIdx[i] = (unsigned short)gidx[(size_t)n * G_DIM + i];
    __syncthreads();

    const float* Wn = W + (size_t)n * G_DIM * O_DIM;
    const int g8 = lane >> 3, i8 = lane & 7;
    const int a_krow = (g8 >> 1) * 8 + i8, a_mcol = (g8 & 1) * 8;
    const int b_krow = (g8 & 1) * 8 + i8, b_ncol = (g8 >> 1) * 8;

    float acc[4][2][4];
#pragma unroll
    for (int i = 0; i < 4; i++)
#pragma unroll
        for (int j = 0; j < 2; j++)
#pragma unroll
            for (int q = 0; q < 4; q++) acc[i][j][q] = 0.0f;

    auto ldg = [&](int ch, uint4& ah, uint4& al, float4& p0) {
        int k0 = ch * 16;
        int gi = sIdx[k0 + lrowA];
        ah = *(const uint4*)&g_xT_hi[(size_t)gi * B_DIM + bbase + lcolA];
        al = *(const uint4*)&g_xT_lo[(size_t)gi * B_DIM + bbase + lcolA];
        p0 = *(const float4*)&Wn[(size_t)(k0 + kkB) * O_DIM + obase + colB];
    };
    auto sts = [&](int buf, uint4 ah, uint4 al, float4 p0) {
        *(uint4*)&As[buf][0][lrowA][lcolA] = ah;
        *(uint4*)&As[buf][1][lrowA][lcolA] = al;
        unsigned short h0 = __half_as_ushort(__float2half_rn(p0.x));
        unsigned short h1 = __half_as_ushort(__float2half_rn(p0.y));
        unsigned short h2 = __half_as_ushort(__float2half_rn(p0.z));
        unsigned short h3 = __half_as_ushort(__float2half_rn(p0.w));
        *(uint2*)&Bs[buf][kkB][colB] =
            make_uint2((uint32_t)h0 | ((uint32_t)h1 << 16), (uint32_t)h2 | ((uint32_t)h3 << 16));
    };
    auto compute = [&](int buf) {
        uint32_t af[2][4][4], bf[4];
#pragma unroll
        for (int v = 0; v < 2; v++)
#pragma unroll
            for (int mt = 0; mt < 4; mt++)
                ldsm4t(af[v][mt], sptr(&As[buf][v][a_krow][wm + mt * 16 + a_mcol]));
        ldsm4t(bf, sptr(&Bs[buf][b_krow][wn + b_ncol]));
#pragma unroll
        for (int mt = 0; mt < 4; mt++)
#pragma unroll
            for (int nt = 0; nt < 2; nt++) {
                mma16816h(acc[mt][nt], af[0][mt], &bf[nt * 2]);
                mma16816h(acc[mt][nt], af[1][mt], &bf[nt * 2]);
            }
    };

    uint4 Ah0, Al0, Ah1, Al1;
    float4 B00, B10;
    ldg(0, Ah0, Al0, B00);
    sts(0, Ah0, Al0, B00);
    ldg(1, Ah0, Al0, B00);
    __syncthreads();

    const int NCHUNK = G_DIM / 16;  // 128
    for (int ch = 0; ch < NCHUNK; ch += 2) {
        if (ch + 2 < NCHUNK) ldg(ch + 2, Ah1, Al1, B10);
        compute(0);
        sts(1, Ah0, Al0, B00);
        __syncthreads();
        if (ch + 3 < NCHUNK) ldg(ch + 3, Ah0, Al0, B00);
        compute(1);
        if (ch + 2 < NCHUNK) sts(0, Ah1, Al1, B10);
        __syncthreads();
    }

    // epilogue: H -> (hi,lo) bf16, row-major [B][NO]
    const int r = lane >> 2, c = (lane & 3) * 2;
#pragma unroll
    for (int mt = 0; mt < 4; mt++)
#pragma unroll
        for (int nt = 0; nt < 2; nt++) {
            int ocol = obase + wn + nt * 8 + c;
            float bv0 = bias[n * O_DIM + ocol], bv1 = bias[n * O_DIM + ocol + 1];
            int b0 = bbase + wm + mt * 16 + r;
#pragma unroll
            for (int q = 0; q < 2; q++) {
                float h0 = acc[mt][nt][q*2] + bv0, h1 = acc[mt][nt][q*2+1] + bv1;
                unsigned short hh0, hl0, hh1, hl1;
                fsplit(h0, hh0, hl0); fsplit(h1, hh1, hl1);
                size_t base = (size_t)(b0 + q*8) * NO_DIM + (size_t)n * O_DIM + ocol;
                *(uint32_t*)&g_H_hi[base] = (uint32_t)hh0 | ((uint32_t)hh1 << 16);
                *(uint32_t*)&g_H_lo[base] = (uint32_t)hl0 | ((uint32_t)hl1 << 16);
            }
        }
}

// ---------------------------------------------------------------- GEMM2 split-K (bf16 3-term, proven, prefetch-2)
__global__ __launch_bounds__(256, 1) void gemm2_kernel(const float* __restrict__ W3)
{
    __shared__ alignas(16) unsigned short As[2][2][128][24];
    __shared__ alignas(16) unsigned short Bs[2][2][16][136];

    const int s = blockIdx.z, bbase = blockIdx.x * 128, ebase = blockIdx.y * 128;
    const int tid = threadIdx.x, lane = tid & 31, warp = tid >> 5;
    const int wm = (warp & 1) * 64, wn = (warp >> 1) * 32;
    const int arow = tid >> 1, ahalf = (tid & 1) * 8;
    const int kkB = tid >> 5, colB = (tid & 31) * 4;
    const int g8 = lane >> 3, i8 = lane & 7;
    const int a_mrow = (g8 & 1) * 8 + i8, a_kcol = (g8 >> 1) * 8;
    const int b_krow = (g8 & 1) * 8 + i8, b_ncol = (g8 >> 1) * 8;

    float acc[4][4][4];
#pragma unroll
    for (int i = 0; i < 4; i++)
#pragma unroll
        for (int j = 0; j < 4; j++)
#pragma unroll
            for (int q = 0; q < 4; q++) acc[i][j][q] = 0.0f;

    const int kbeg = s * 256;

    auto ldg = [&](int ch, uint4& ah, uint4& al, float4& p0, float4& p1) {
        int k0 = kbeg + ch * 16;
        ah = *(const uint4*)&g_H_hi[(size_t)(bbase + arow) * NO_DIM + k0 + ahalf];
        al = *(const uint4*)&g_H_lo[(size_t)(bbase + arow) * NO_DIM + k0 + ahalf];
        p0 = *(const float4*)&W3[(size_t)(k0 + kkB) * E_DIM + ebase + colB];
        p1 = *(const float4*)&W3[(size_t)(k0 + kkB + 8) * E_DIM + ebase + colB];
    };
    auto sts = [&](int buf, uint4 ah, uint4 al, float4 p0, float4 p1) {
        *(uint4*)&As[buf][0][arow][ahalf] = ah;
        *(uint4*)&As[buf][1][arow][ahalf] = al;
        split_store8(p0, &Bs[buf][0][kkB][colB],   &Bs[buf][1][kkB][colB]);
        split_store8(p1, &Bs[buf][0][kkB+8][colB], &Bs[buf][1][kkB+8][colB]);
    };
    auto compute = [&](int buf) {
        uint32_t af[2][4][4], bfv[2][2][4];
#pragma unroll
        for (int v = 0; v < 2; v++)
#pragma unroll
            for (int mt = 0; mt < 4; mt++)
                ldsm4(af[v][mt], sptr(&As[buf][v][wm + mt * 16 + a_mrow][a_kcol]));
#pragma unroll
        for (int v = 0; v < 2; v++)
#pragma unroll
            for (int np = 0; np < 2; np++)
                ldsm4t(bfv[v][np], sptr(&Bs[buf][v][b_krow][wn + np * 16 + b_ncol]));
#pragma unroll
        for (int mt = 0; mt < 4; mt++)
#pragma unroll
            for (int nt = 0; nt < 4; nt++) {
                const uint32_t* bh = &bfv[0][nt >> 1][(nt & 1) * 2];
                const uint32_t* bl = &bfv[1][nt >> 1][(nt & 1) * 2];
                mma16816(acc[mt][nt], af[0][mt], bh);
                mma16816(acc[mt][nt], af[0][mt], bl);
                mma16816(acc[mt][nt], af[1][mt], bh);
            }
    };

    uint4 Ah0, Al0, Ah1, Al1;
    float4 B00, B01, B10, B11;
    ldg(0, Ah0, Al0, B00, B01);
    sts(0, Ah0, Al0, B00, B01);
    ldg(1, Ah0, Al0, B00, B01);
    __syncthreads();

    const int NCHUNK = 16;
    for (int ch = 0; ch < NCHUNK; ch += 2) {
        if (ch + 2 < NCHUNK) ldg(ch + 2, Ah1, Al1, B10, B11);
        compute(0);
        sts(1, Ah0, Al0, B00, B01);
        __syncthreads();
        if (ch + 3 < NCHUNK) ldg(ch + 3, Ah0, Al0, B00, B01);
        compute(1);
        if (ch + 2 < NCHUNK) sts(0, Ah1, Al1, B10, B11);
        __syncthreads();
    }

    float* Ps = g_P + (size_t)s * B_DIM * E_DIM;
    const int r = lane >> 2, c = (lane & 3) * 2;
#pragma unroll
    for (int mt = 0; mt < 4; mt++)
#pragma unroll
        for (int nt = 0; nt < 4; nt++) {
            int ecol = ebase + wn + nt * 8 + c;
            int b0 = bbase + wm + mt * 16 + r;
            *(float2*)&Ps[(size_t)b0 * E_DIM + ecol] = make_float2(acc[mt][nt][0], acc[mt][nt][1]);
            *(float2*)&Ps[(size_t)(b0 + 8) * E_DIM + ecol] = make_float2(acc[mt][nt][2], acc[mt][nt][3]);
        }
}

// ---------------------------------------------------------------- reduce
__global__ __launch_bounds__(256) void reduce_kernel(const float* __restrict__ b3, float* __restrict__ out) {
    int i4 = blockIdx.x * 256 + threadIdx.x;
    int e4 = i4 & (E_DIM / 4 - 1);
    float4 sum = ((const float4*)b3)[e4];
#pragma unroll
    for (int s = 0; s < N_DIM; s++) {
        float4 p = ((const float4*)g_P)[(size_t)s * (B_DIM * E_DIM / 4) + i4];
        sum.x += p.x; sum.y += p.y; sum.z += p.z; sum.w += p.w;
    }
    sum.x = (sum.x >= 0.f) ? sum.x : NEG_SLOPE * sum.x;
    sum.y = (sum.y >= 0.f) ? sum.y : NEG_SLOPE * sum.y;
    sum.z = (sum.z >= 0.f) ? sum.z : NEG_SLOPE * sum.z;
    sum.w = (sum.w >= 0.f) ? sum.w : NEG_SLOPE * sum.w;
    ((float4*)out)[i4] = sum;
}

// ----------------------------------------------------------------
extern "C" void kernel_launch(void* const* d_in, const int* in_sizes, int n_in,
                              void* d_out, int out_size) {
    const float* x    = (const float*)d_in[0];
    const int*   gidx = (const int*)  d_in[1];
    const float* W    = (const float*)d_in[2];
    const float* bias = (const float*)d_in[3];
    const float* W3   = (const float*)d_in[4];
    const float* b3   = (const float*)d_in[5];
    float* out = (float*)d_out;

    {
        dim3 grid(D_DIM / 64, B_DIM / 64);
        transpose_split_kernel<<<grid, 256>>>(x);
    }
    {
        dim3 grid(B_DIM / 128, O_DIM / 64, N_DIM);    // (2,4,41) = 328 CTAs
        gemm1_kernel<<<grid, 256>>>(gidx, W, bias);
    }
    {
        dim3 grid(B_DIM / 128, E_DIM / 128, N_DIM);   // (2,4,41)
        gemm2_kernel<<<grid, 256>>>(W3);
    }
    {
        reduce_kernel<<<(B_DIM * E_DIM / 4) / 256, 256>>>(b3, out);
    }
}

// round 10
// speedup vs baseline: 3.9181x; 1.0526x over previous
#include <cuda_runtime.h>
#include <cuda_bf16.h>
#include <cuda_fp16.h>
#include <cstdint>

#define B_DIM 256
#define D_DIM 65536
#define N_DIM 41
#define G_DIM 2048
#define O_DIM 256
#define E_DIM 512
#define NO_DIM (N_DIM * O_DIM)
#define NEG_SLOPE 0.2f

// statics: 96.25 MB (proven level). xT and H hold fp16 bits (hi,lo).
__device__ unsigned short g_xT_hi[(size_t)D_DIM * B_DIM];
__device__ unsigned short g_xT_lo[(size_t)D_DIM * B_DIM];
__device__ unsigned short g_H_hi[(size_t)B_DIM * NO_DIM];
__device__ unsigned short g_H_lo[(size_t)B_DIM * NO_DIM];
__device__ float g_P[(size_t)N_DIM * B_DIM * E_DIM];

// ---------------------------------------------------------------- helpers
__device__ __forceinline__ uint32_t sptr(const void* p) {
    return (uint32_t)__cvta_generic_to_shared(p);
}
// fp16 split
__device__ __forceinline__ void hsplit(float v, unsigned short& h, unsigned short& l) {
    __half hh = __float2half_rn(v);
    h = __half_as_ushort(hh);
    l = __half_as_ushort(__float2half_rn(v - __half2float(hh)));
}
__device__ __forceinline__ void ldsm4t(uint32_t* r, uint32_t a) {
    asm volatile("ldmatrix.sync.aligned.m8n8.x4.trans.shared.b16 {%0,%1,%2,%3},[%4];"
                 : "=r"(r[0]), "=r"(r[1]), "=r"(r[2]), "=r"(r[3]) : "r"(a));
}
__device__ __forceinline__ void ldsm4(uint32_t* r, uint32_t a) {
    asm volatile("ldmatrix.sync.aligned.m8n8.x4.shared.b16 {%0,%1,%2,%3},[%4];"
                 : "=r"(r[0]), "=r"(r[1]), "=r"(r[2]), "=r"(r[3]) : "r"(a));
}
// fp16 MMA
__device__ __forceinline__ void mma16816h(float* c, const uint32_t* a, const uint32_t* b) {
    asm volatile("mma.sync.aligned.m16n8k16.row.col.f32.f16.f16.f32 "
                 "{%0,%1,%2,%3},{%4,%5,%6,%7},{%8,%9},{%0,%1,%2,%3};"
                 : "+f"(c[0]), "+f"(c[1]), "+f"(c[2]), "+f"(c[3])
                 : "r"(a[0]), "r"(a[1]), "r"(a[2]), "r"(a[3]), "r"(b[0]), "r"(b[1]));
}

// ---------------------------------------------------------------- transpose + fp16-split x
__global__ __launch_bounds__(256) void transpose_split_kernel(const float* __restrict__ x) {
    __shared__ float tile[64][65];
    int d0 = blockIdx.x * 64, b0 = blockIdx.y * 64;
    int t = threadIdx.x;
    int br = t / 16, dc = (t % 16) * 4;
#pragma unroll
    for (int p = 0; p < 4; p++) {
        int b = br + p * 16;
        float4 v = *(const float4*)&x[(size_t)(b0 + b) * D_DIM + d0 + dc];
        tile[b][dc] = v.x; tile[b][dc+1] = v.y; tile[b][dc+2] = v.z; tile[b][dc+3] = v.w;
    }
    __syncthreads();
    int dr = t / 16, bc = (t % 16) * 4;
#pragma unroll
    for (int p = 0; p < 4; p++) {
        int d = dr + p * 16;
        unsigned short h0,h1,h2,h3,l0,l1,l2,l3;
        hsplit(tile[bc][d], h0, l0);   hsplit(tile[bc+1][d], h1, l1);
        hsplit(tile[bc+2][d], h2, l2); hsplit(tile[bc+3][d], h3, l3);
        size_t off = (size_t)(d0 + d) * B_DIM + b0 + bc;
        *(uint2*)&g_xT_hi[off] = make_uint2((uint32_t)h0|((uint32_t)h1<<16), (uint32_t)h2|((uint32_t)h3<<16));
        *(uint2*)&g_xT_lo[off] = make_uint2((uint32_t)l0|((uint32_t)l1<<16), (uint32_t)l2|((uint32_t)l3<<16));
    }
}

// ---------------------------------------------------------------- GEMM1 (fp16 2-term, tile 128x64, prefetch-2, occ 2)
__global__ __launch_bounds__(256, 2) void gemm1_kernel(
    const int* __restrict__ gidx, const float* __restrict__ W, const float* __restrict__ bias)
{
    __shared__ unsigned short sIdx[G_DIM];                        // 4 KB
    __shared__ alignas(16) unsigned short As[2][2][16][136];      // 17 KB
    __shared__ alignas(16) unsigned short Bs[2][16][72];          // 4.5 KB

    const int n     = blockIdx.z;
    const int bbase = blockIdx.x * 128;
    const int obase = blockIdx.y * 64;
    const int tid = threadIdx.x, lane = tid & 31, warp = tid >> 5;
    const int wm = (warp & 1) * 64, wn = (warp >> 1) * 16;
    const int lrowA = tid >> 4, lcolA = (tid & 15) * 8;
    const int kkB = tid >> 4, colB = (tid & 15) * 4;

    for (int i = tid; i < G_DIM; i += 256)
        sIdx[i] = (unsigned short)gidx[(size_t)n * G_DIM + i];
    __syncthreads();

    const float* Wn = W + (size_t)n * G_DIM * O_DIM;
    const int g8 = lane >> 3, i8 = lane & 7;
    const int a_krow = (g8 >> 1) * 8 + i8, a_mcol = (g8 & 1) * 8;
    const int b_krow = (g8 & 1) * 8 + i8, b_ncol = (g8 >> 1) * 8;

    float acc[4][2][4];
#pragma unroll
    for (int i = 0; i < 4; i++)
#pragma unroll
        for (int j = 0; j < 2; j++)
#pragma unroll
            for (int q = 0; q < 4; q++) acc[i][j][q] = 0.0f;

    auto ldg = [&](int ch, uint4& ah, uint4& al, float4& p0) {
        int k0 = ch * 16;
        int gi = sIdx[k0 + lrowA];
        ah = *(const uint4*)&g_xT_hi[(size_t)gi * B_DIM + bbase + lcolA];
        al = *(const uint4*)&g_xT_lo[(size_t)gi * B_DIM + bbase + lcolA];
        p0 = *(const float4*)&Wn[(size_t)(k0 + kkB) * O_DIM + obase + colB];
    };
    auto sts = [&](int buf, uint4 ah, uint4 al, float4 p0) {
        *(uint4*)&As[buf][0][lrowA][lcolA] = ah;
        *(uint4*)&As[buf][1][lrowA][lcolA] = al;
        unsigned short h0 = __half_as_ushort(__float2half_rn(p0.x));
        unsigned short h1 = __half_as_ushort(__float2half_rn(p0.y));
        unsigned short h2 = __half_as_ushort(__float2half_rn(p0.z));
        unsigned short h3 = __half_as_ushort(__float2half_rn(p0.w));
        *(uint2*)&Bs[buf][kkB][colB] =
            make_uint2((uint32_t)h0 | ((uint32_t)h1 << 16), (uint32_t)h2 | ((uint32_t)h3 << 16));
    };
    auto compute = [&](int buf) {
        uint32_t af[2][4][4], bf[4];
#pragma unroll
        for (int v = 0; v < 2; v++)
#pragma unroll
            for (int mt = 0; mt < 4; mt++)
                ldsm4t(af[v][mt], sptr(&As[buf][v][a_krow][wm + mt * 16 + a_mcol]));
        ldsm4t(bf, sptr(&Bs[buf][b_krow][wn + b_ncol]));
#pragma unroll
        for (int mt = 0; mt < 4; mt++)
#pragma unroll
            for (int nt = 0; nt < 2; nt++) {
                mma16816h(acc[mt][nt], af[0][mt], &bf[nt * 2]);
                mma16816h(acc[mt][nt], af[1][mt], &bf[nt * 2]);
            }
    };

    uint4 Ah0, Al0, Ah1, Al1;
    float4 B00, B10;
    ldg(0, Ah0, Al0, B00);
    sts(0, Ah0, Al0, B00);
    ldg(1, Ah0, Al0, B00);
    __syncthreads();

    const int NCHUNK = G_DIM / 16;  // 128
    for (int ch = 0; ch < NCHUNK; ch += 2) {
        if (ch + 2 < NCHUNK) ldg(ch + 2, Ah1, Al1, B10);
        compute(0);
        sts(1, Ah0, Al0, B00);
        __syncthreads();
        if (ch + 3 < NCHUNK) ldg(ch + 3, Ah0, Al0, B00);
        compute(1);
        if (ch + 2 < NCHUNK) sts(0, Ah1, Al1, B10);
        __syncthreads();
    }

    // epilogue: H -> (hi,lo) fp16, row-major [B][NO]
    const int r = lane >> 2, c = (lane & 3) * 2;
#pragma unroll
    for (int mt = 0; mt < 4; mt++)
#pragma unroll
        for (int nt = 0; nt < 2; nt++) {
            int ocol = obase + wn + nt * 8 + c;
            float bv0 = bias[n * O_DIM + ocol], bv1 = bias[n * O_DIM + ocol + 1];
            int b0 = bbase + wm + mt * 16 + r;
#pragma unroll
            for (int q = 0; q < 2; q++) {
                float h0 = acc[mt][nt][q*2] + bv0, h1 = acc[mt][nt][q*2+1] + bv1;
                unsigned short hh0, hl0, hh1, hl1;
                hsplit(h0, hh0, hl0); hsplit(h1, hh1, hl1);
                size_t base = (size_t)(b0 + q*8) * NO_DIM + (size_t)n * O_DIM + ocol;
                *(uint32_t*)&g_H_hi[base] = (uint32_t)hh0 | ((uint32_t)hh1 << 16);
                *(uint32_t*)&g_H_lo[base] = (uint32_t)hl0 | ((uint32_t)hl1 << 16);
            }
        }
}

// ---------------------------------------------------------------- GEMM2 split-K (fp16 2-term, prefetch-2, occ 2)
__global__ __launch_bounds__(256, 2) void gemm2_kernel(const float* __restrict__ W3)
{
    __shared__ alignas(16) unsigned short As[2][2][128][24];   // 24 KB
    __shared__ alignas(16) unsigned short Bs[2][16][136];      // 8.5 KB

    const int s = blockIdx.z, bbase = blockIdx.x * 128, ebase = blockIdx.y * 128;
    const int tid = threadIdx.x, lane = tid & 31, warp = tid >> 5;
    const int wm = (warp & 1) * 64, wn = (warp >> 1) * 32;
    const int arow = tid >> 1, ahalf = (tid & 1) * 8;
    const int kkB = tid >> 5, colB = (tid & 31) * 4;
    const int g8 = lane >> 3, i8 = lane & 7;
    const int a_mrow = (g8 & 1) * 8 + i8, a_kcol = (g8 >> 1) * 8;
    const int b_krow = (g8 & 1) * 8 + i8, b_ncol = (g8 >> 1) * 8;

    float acc[4][4][4];
#pragma unroll
    for (int i = 0; i < 4; i++)
#pragma unroll
        for (int j = 0; j < 4; j++)
#pragma unroll
            for (int q = 0; q < 4; q++) acc[i][j][q] = 0.0f;

    const int kbeg = s * 256;

    auto ldg = [&](int ch, uint4& ah, uint4& al, float4& p0, float4& p1) {
        int k0 = kbeg + ch * 16;
        ah = *(const uint4*)&g_H_hi[(size_t)(bbase + arow) * NO_DIM + k0 + ahalf];
        al = *(const uint4*)&g_H_lo[(size_t)(bbase + arow) * NO_DIM + k0 + ahalf];
        p0 = *(const float4*)&W3[(size_t)(k0 + kkB) * E_DIM + ebase + colB];
        p1 = *(const float4*)&W3[(size_t)(k0 + kkB + 8) * E_DIM + ebase + colB];
    };
    auto cvt4 = [](float4 v) {
        unsigned short h0 = __half_as_ushort(__float2half_rn(v.x));
        unsigned short h1 = __half_as_ushort(__float2half_rn(v.y));
        unsigned short h2 = __half_as_ushort(__float2half_rn(v.z));
        unsigned short h3 = __half_as_ushort(__float2half_rn(v.w));
        return make_uint2((uint32_t)h0 | ((uint32_t)h1 << 16), (uint32_t)h2 | ((uint32_t)h3 << 16));
    };
    auto sts = [&](int buf, uint4 ah, uint4 al, float4 p0, float4 p1) {
        *(uint4*)&As[buf][0][arow][ahalf] = ah;
        *(uint4*)&As[buf][1][arow][ahalf] = al;
        *(uint2*)&Bs[buf][kkB][colB]     = cvt4(p0);
        *(uint2*)&Bs[buf][kkB + 8][colB] = cvt4(p1);
    };
    auto compute = [&](int buf) {
        uint32_t af[2][4][4], bfv[2][4];
#pragma unroll
        for (int v = 0; v < 2; v++)
#pragma unroll
            for (int mt = 0; mt < 4; mt++)
                ldsm4(af[v][mt], sptr(&As[buf][v][wm + mt * 16 + a_mrow][a_kcol]));
#pragma unroll
        for (int np = 0; np < 2; np++)
            ldsm4t(bfv[np], sptr(&Bs[buf][b_krow][wn + np * 16 + b_ncol]));
#pragma unroll
        for (int mt = 0; mt < 4; mt++)
#pragma unroll
            for (int nt = 0; nt < 4; nt++) {
                const uint32_t* bh = &bfv[nt >> 1][(nt & 1) * 2];
                mma16816h(acc[mt][nt], af[0][mt], bh);
                mma16816h(acc[mt][nt], af[1][mt], bh);
            }
    };

    uint4 Ah0, Al0, Ah1, Al1;
    float4 B00, B01, B10, B11;
    ldg(0, Ah0, Al0, B00, B01);
    sts(0, Ah0, Al0, B00, B01);
    ldg(1, Ah0, Al0, B00, B01);
    __syncthreads();

    const int NCHUNK = 16;
    for (int ch = 0; ch < NCHUNK; ch += 2) {
        if (ch + 2 < NCHUNK) ldg(ch + 2, Ah1, Al1, B10, B11);
        compute(0);
        sts(1, Ah0, Al0, B00, B01);
        __syncthreads();
        if (ch + 3 < NCHUNK) ldg(ch + 3, Ah0, Al0, B00, B01);
        compute(1);
        if (ch + 2 < NCHUNK) sts(0, Ah1, Al1, B10, B11);
        __syncthreads();
    }

    float* Ps = g_P + (size_t)s * B_DIM * E_DIM;
    const int r = lane >> 2, c = (lane & 3) * 2;
#pragma unroll
    for (int mt = 0; mt < 4; mt++)
#pragma unroll
        for (int nt = 0; nt < 4; nt++) {
            int ecol = ebase + wn + nt * 8 + c;
            int b0 = bbase + wm + mt * 16 + r;
            *(float2*)&Ps[(size_t)b0 * E_DIM + ecol] = make_float2(acc[mt][nt][0], acc[mt][nt][1]);
            *(float2*)&Ps[(size_t)(b0 + 8) * E_DIM + ecol] = make_float2(acc[mt][nt][2], acc[mt][nt][3]);
        }
}

// ---------------------------------------------------------------- reduce
__global__ __launch_bounds__(256) void reduce_kernel(const float* __restrict__ b3, float* __restrict__ out) {
    int i4 = blockIdx.x * 256 + threadIdx.x;
    int e4 = i4 & (E_DIM / 4 - 1);
    float4 sum = ((const float4*)b3)[e4];
#pragma unroll
    for (int s = 0; s < N_DIM; s++) {
        float4 p = ((const float4*)g_P)[(size_t)s * (B_DIM * E_DIM / 4) + i4];
        sum.x += p.x; sum.y += p.y; sum.z += p.z; sum.w += p.w;
    }
    sum.x = (sum.x >= 0.f) ? sum.x : NEG_SLOPE * sum.x;
    sum.y = (sum.y >= 0.f) ? sum.y : NEG_SLOPE * sum.y;
    sum.z = (sum.z >= 0.f) ? sum.z : NEG_SLOPE * sum.z;
    sum.w = (sum.w >= 0.f) ? sum.w : NEG_SLOPE * sum.w;
    ((float4*)out)[i4] = sum;
}

// ----------------------------------------------------------------
extern "C" void kernel_launch(void* const* d_in, const int* in_sizes, int n_in,
                              void* d_out, int out_size) {
    const float* x    = (const float*)d_in[0];
    const int*   gidx = (const int*)  d_in[1];
    const float* W    = (const float*)d_in[2];
    const float* bias = (const float*)d_in[3];
    const float* W3   = (const float*)d_in[4];
    const float* b3   = (const float*)d_in[5];
    float* out = (float*)d_out;

    {
        dim3 grid(D_DIM / 64, B_DIM / 64);
        transpose_split_kernel<<<grid, 256>>>(x);
    }
    {
        dim3 grid(B_DIM / 128, O_DIM / 64, N_DIM);    // (2,4,41) = 328 CTAs
        gemm1_kernel<<<grid, 256>>>(gidx, W, bias);
    }
    {
        dim3 grid(B_DIM / 128, E_DIM / 128, N_DIM);   // (2,4,41)
        gemm2_kernel<<<grid, 256>>>(W3);
    }
    {
        reduce_kernel<<<(B_DIM * E_DIM / 4) / 256, 256>>>(b3, out);
    }
}

// round 11
// speedup vs baseline: 4.5980x; 1.1735x over previous
#include <cuda_runtime.h>
#include <cuda_fp16.h>
#include <cstdint>

#define B_DIM 256
#define D_DIM 65536
#define N_DIM 41
#define G_DIM 2048
#define O_DIM 256
#define E_DIM 512
#define NO_DIM (N_DIM * O_DIM)
#define NEG_SLOPE 0.2f

// statics ~59 MB (below proven 96 MB level)
__device__ unsigned short g_xT[(size_t)D_DIM * B_DIM];     // 32 MB fp16 bits
__device__ unsigned short g_H[(size_t)B_DIM * NO_DIM];     // 5.4 MB fp16 bits
__device__ float g_P[(size_t)N_DIM * B_DIM * E_DIM];       // 21.5 MB

// ---------------------------------------------------------------- helpers
__device__ __forceinline__ uint32_t sptr(const void* p) {
    return (uint32_t)__cvta_generic_to_shared(p);
}
__device__ __forceinline__ void ldsm4t(uint32_t* r, uint32_t a) {
    asm volatile("ldmatrix.sync.aligned.m8n8.x4.trans.shared.b16 {%0,%1,%2,%3},[%4];"
                 : "=r"(r[0]), "=r"(r[1]), "=r"(r[2]), "=r"(r[3]) : "r"(a));
}
__device__ __forceinline__ void ldsm4(uint32_t* r, uint32_t a) {
    asm volatile("ldmatrix.sync.aligned.m8n8.x4.shared.b16 {%0,%1,%2,%3},[%4];"
                 : "=r"(r[0]), "=r"(r[1]), "=r"(r[2]), "=r"(r[3]) : "r"(a));
}
__device__ __forceinline__ void mma16816h(float* c, const uint32_t* a, const uint32_t* b) {
    asm volatile("mma.sync.aligned.m16n8k16.row.col.f32.f16.f16.f32 "
                 "{%0,%1,%2,%3},{%4,%5,%6,%7},{%8,%9},{%0,%1,%2,%3};"
                 : "+f"(c[0]), "+f"(c[1]), "+f"(c[2]), "+f"(c[3])
                 : "r"(a[0]), "r"(a[1]), "r"(a[2]), "r"(a[3]), "r"(b[0]), "r"(b[1]));
}
__device__ __forceinline__ uint32_t pack2h(float a, float b) {
    return (uint32_t)__half_as_ushort(__float2half_rn(a)) |
           ((uint32_t)__half_as_ushort(__float2half_rn(b)) << 16);
}

// ---------------------------------------------------------------- transpose x -> fp16 xT [D][B]
__global__ __launch_bounds__(256) void transpose_kernel(const float* __restrict__ x) {
    __shared__ float tile[64][65];
    int d0 = blockIdx.x * 64, b0 = blockIdx.y * 64;
    int t = threadIdx.x;
    int br = t / 16, dc = (t % 16) * 4;
#pragma unroll
    for (int p = 0; p < 4; p++) {
        int b = br + p * 16;
        float4 v = *(const float4*)&x[(size_t)(b0 + b) * D_DIM + d0 + dc];
        tile[b][dc] = v.x; tile[b][dc+1] = v.y; tile[b][dc+2] = v.z; tile[b][dc+3] = v.w;
    }
    __syncthreads();
    int dr = t / 16, bc = (t % 16) * 4;
#pragma unroll
    for (int p = 0; p < 4; p++) {
        int d = dr + p * 16;
        size_t off = (size_t)(d0 + d) * B_DIM + b0 + bc;
        *(uint2*)&g_xT[off] = make_uint2(pack2h(tile[bc][d],   tile[bc+1][d]),
                                         pack2h(tile[bc+2][d], tile[bc+3][d]));
    }
}

// ---------------------------------------------------------------- GEMM1 (fp16 1-term, tile 128x64, prefetch-2, occ 2)
// H[b][n*256+o] = sum_g xT[idx][b] * W[n][g][o] + bias
__global__ __launch_bounds__(256, 2) void gemm1_kernel(
    const int* __restrict__ gidx, const float* __restrict__ W, const float* __restrict__ bias)
{
    __shared__ unsigned short sIdx[G_DIM];                      // 4 KB
    __shared__ alignas(16) unsigned short As[2][16][136];       // 8.5 KB
    __shared__ alignas(16) unsigned short Bs[2][16][72];        // 4.5 KB

    const int n     = blockIdx.z;
    const int bbase = blockIdx.x * 128;
    const int obase = blockIdx.y * 64;
    const int tid = threadIdx.x, lane = tid & 31, warp = tid >> 5;
    const int wm = (warp & 1) * 64, wn = (warp >> 1) * 16;
    const int lrowA = tid >> 4, lcolA = (tid & 15) * 8;
    const int kkB = tid >> 4, colB = (tid & 15) * 4;

    for (int i = tid; i < G_DIM; i += 256)
        sIdx[i] = (unsigned short)gidx[(size_t)n * G_DIM + i];
    __syncthreads();

    const float* Wn = W + (size_t)n * G_DIM * O_DIM;
    const int g8 = lane >> 3, i8 = lane & 7;
    const int a_krow = (g8 >> 1) * 8 + i8, a_mcol = (g8 & 1) * 8;
    const int b_krow = (g8 & 1) * 8 + i8, b_ncol = (g8 >> 1) * 8;

    float acc[4][2][4];
#pragma unroll
    for (int i = 0; i < 4; i++)
#pragma unroll
        for (int j = 0; j < 2; j++)
#pragma unroll
            for (int q = 0; q < 4; q++) acc[i][j][q] = 0.0f;

    auto ldg = [&](int ch, uint4& ah, float4& p0) {
        int k0 = ch * 16;
        int gi = sIdx[k0 + lrowA];
        ah = *(const uint4*)&g_xT[(size_t)gi * B_DIM + bbase + lcolA];
        p0 = *(const float4*)&Wn[(size_t)(k0 + kkB) * O_DIM + obase + colB];
    };
    auto sts = [&](int buf, uint4 ah, float4 p0) {
        *(uint4*)&As[buf][lrowA][lcolA] = ah;
        *(uint2*)&Bs[buf][kkB][colB] = make_uint2(pack2h(p0.x, p0.y), pack2h(p0.z, p0.w));
    };
    auto compute = [&](int buf) {
        uint32_t af[4][4], bf[4];
#pragma unroll
        for (int mt = 0; mt < 4; mt++)
            ldsm4t(af[mt], sptr(&As[buf][a_krow][wm + mt * 16 + a_mcol]));
        ldsm4t(bf, sptr(&Bs[buf][b_krow][wn + b_ncol]));
#pragma unroll
        for (int mt = 0; mt < 4; mt++)
#pragma unroll
            for (int nt = 0; nt < 2; nt++)
                mma16816h(acc[mt][nt], af[mt], &bf[nt * 2]);
    };

    uint4 Ah0, Ah1;
    float4 B00, B10;
    ldg(0, Ah0, B00);
    sts(0, Ah0, B00);
    ldg(1, Ah0, B00);
    __syncthreads();

    const int NCHUNK = G_DIM / 16;  // 128
    for (int ch = 0; ch < NCHUNK; ch += 2) {
        if (ch + 2 < NCHUNK) ldg(ch + 2, Ah1, B10);
        compute(0);
        sts(1, Ah0, B00);
        __syncthreads();
        if (ch + 3 < NCHUNK) ldg(ch + 3, Ah0, B00);
        compute(1);
        if (ch + 2 < NCHUNK) sts(0, Ah1, B10);
        __syncthreads();
    }

    // epilogue: H -> fp16, row-major [B][NO]
    const int r = lane >> 2, c = (lane & 3) * 2;
#pragma unroll
    for (int mt = 0; mt < 4; mt++)
#pragma unroll
        for (int nt = 0; nt < 2; nt++) {
            int ocol = obase + wn + nt * 8 + c;
            float bv0 = bias[n * O_DIM + ocol], bv1 = bias[n * O_DIM + ocol + 1];
            int b0 = bbase + wm + mt * 16 + r;
#pragma unroll
            for (int q = 0; q < 2; q++) {
                size_t base = (size_t)(b0 + q*8) * NO_DIM + (size_t)n * O_DIM + ocol;
                *(uint32_t*)&g_H[base] =
                    pack2h(acc[mt][nt][q*2] + bv0, acc[mt][nt][q*2+1] + bv1);
            }
        }
}

// ---------------------------------------------------------------- GEMM2 split-K (fp16 1-term, prefetch-2, occ 2)
__global__ __launch_bounds__(256, 2) void gemm2_kernel(const float* __restrict__ W3)
{
    __shared__ alignas(16) unsigned short As[2][128][24];   // 12 KB
    __shared__ alignas(16) unsigned short Bs[2][16][136];   // 8.5 KB

    const int s = blockIdx.z, bbase = blockIdx.x * 128, ebase = blockIdx.y * 128;
    const int tid = threadIdx.x, lane = tid & 31, warp = tid >> 5;
    const int wm = (warp & 1) * 64, wn = (warp >> 1) * 32;
    const int arow = tid >> 1, ahalf = (tid & 1) * 8;
    const int kkB = tid >> 5, colB = (tid & 31) * 4;
    const int g8 = lane >> 3, i8 = lane & 7;
    const int a_mrow = (g8 & 1) * 8 + i8, a_kcol = (g8 >> 1) * 8;
    const int b_krow = (g8 & 1) * 8 + i8, b_ncol = (g8 >> 1) * 8;

    float acc[4][4][4];
#pragma unroll
    for (int i = 0; i < 4; i++)
#pragma unroll
        for (int j = 0; j < 4; j++)
#pragma unroll
            for (int q = 0; q < 4; q++) acc[i][j][q] = 0.0f;

    const int kbeg = s * 256;

    auto ldg = [&](int ch, uint4& ah, float4& p0, float4& p1) {
        int k0 = kbeg + ch * 16;
        ah = *(const uint4*)&g_H[(size_t)(bbase + arow) * NO_DIM + k0 + ahalf];
        p0 = *(const float4*)&W3[(size_t)(k0 + kkB) * E_DIM + ebase + colB];
        p1 = *(const float4*)&W3[(size_t)(k0 + kkB + 8) * E_DIM + ebase + colB];
    };
    auto sts = [&](int buf, uint4 ah, float4 p0, float4 p1) {
        *(uint4*)&As[buf][arow][ahalf] = ah;
        *(uint2*)&Bs[buf][kkB][colB]     = make_uint2(pack2h(p0.x, p0.y), pack2h(p0.z, p0.w));
        *(uint2*)&Bs[buf][kkB + 8][colB] = make_uint2(pack2h(p1.x, p1.y), pack2h(p1.z, p1.w));
    };
    auto compute = [&](int buf) {
        uint32_t af[4][4], bfv[2][4];
#pragma unroll
        for (int mt = 0; mt < 4; mt++)
            ldsm4(af[mt], sptr(&As[buf][wm + mt * 16 + a_mrow][a_kcol]));
#pragma unroll
        for (int np = 0; np < 2; np++)
            ldsm4t(bfv[np], sptr(&Bs[buf][b_krow][wn + np * 16 + b_ncol]));
#pragma unroll
        for (int mt = 0; mt < 4; mt++)
#pragma unroll
            for (int nt = 0; nt < 4; nt++)
                mma16816h(acc[mt][nt], af[mt], &bfv[nt >> 1][(nt & 1) * 2]);
    };

    uint4 Ah0, Ah1;
    float4 B00, B01, B10, B11;
    ldg(0, Ah0, B00, B01);
    sts(0, Ah0, B00, B01);
    ldg(1, Ah0, B00, B01);
    __syncthreads();

    const int NCHUNK = 16;
    for (int ch = 0; ch < NCHUNK; ch += 2) {
        if (ch + 2 < NCHUNK) ldg(ch + 2, Ah1, B10, B11);
        compute(0);
        sts(1, Ah0, B00, B01);
        __syncthreads();
        if (ch + 3 < NCHUNK) ldg(ch + 3, Ah0, B00, B01);
        compute(1);
        if (ch + 2 < NCHUNK) sts(0, Ah1, B10, B11);
        __syncthreads();
    }

    float* Ps = g_P + (size_t)s * B_DIM * E_DIM;
    const int r = lane >> 2, c = (lane & 3) * 2;
#pragma unroll
    for (int mt = 0; mt < 4; mt++)
#pragma unroll
        for (int nt = 0; nt < 4; nt++) {
            int ecol = ebase + wn + nt * 8 + c;
            int b0 = bbase + wm + mt * 16 + r;
            *(float2*)&Ps[(size_t)b0 * E_DIM + ecol] = make_float2(acc[mt][nt][0], acc[mt][nt][1]);
            *(float2*)&Ps[(size_t)(b0 + 8) * E_DIM + ecol] = make_float2(acc[mt][nt][2], acc[mt][nt][3]);
        }
}

// ---------------------------------------------------------------- reduce
__global__ __launch_bounds__(256) void reduce_kernel(const float* __restrict__ b3, float* __restrict__ out) {
    int i4 = blockIdx.x * 256 + threadIdx.x;
    int e4 = i4 & (E_DIM / 4 - 1);
    float4 sum = ((const float4*)b3)[e4];
#pragma unroll
    for (int s = 0; s < N_DIM; s++) {
        float4 p = ((const float4*)g_P)[(size_t)s * (B_DIM * E_DIM / 4) + i4];
        sum.x += p.x; sum.y += p.y; sum.z += p.z; sum.w += p.w;
    }
    sum.x = (sum.x >= 0.f) ? sum.x : NEG_SLOPE * sum.x;
    sum.y = (sum.y >= 0.f) ? sum.y : NEG_SLOPE * sum.y;
    sum.z = (sum.z >= 0.f) ? sum.z : NEG_SLOPE * sum.z;
    sum.w = (sum.w >= 0.f) ? sum.w : NEG_SLOPE * sum.w;
    ((float4*)out)[i4] = sum;
}

// ----------------------------------------------------------------
extern "C" void kernel_launch(void* const* d_in, const int* in_sizes, int n_in,
                              void* d_out, int out_size) {
    const float* x    = (const float*)d_in[0];
    const int*   gidx = (const int*)  d_in[1];
    const float* W    = (const float*)d_in[2];
    const float* bias = (const float*)d_in[3];
    const float* W3   = (const float*)d_in[4];
    const float* b3   = (const float*)d_in[5];
    float* out = (float*)d_out;

    {
        dim3 grid(D_DIM / 64, B_DIM / 64);
        transpose_kernel<<<grid, 256>>>(x);
    }
    {
        dim3 grid(B_DIM / 128, O_DIM / 64, N_DIM);    // (2,4,41) = 328 CTAs
        gemm1_kernel<<<grid, 256>>>(gidx, W, bias);
    }
    {
        dim3 grid(B_DIM / 128, E_DIM / 128, N_DIM);   // (2,4,41)
        gemm2_kernel<<<grid, 256>>>(W3);
    }
    {
        reduce_kernel<<<(B_DIM * E_DIM / 4) / 256, 256>>>(b3, out);
    }
}

// round 12
// speedup vs baseline: 5.9050x; 1.2843x over previous
#include <cuda_runtime.h>
#include <cuda_fp16.h>
#include <cstdint>

#define B_DIM 256
#define D_DIM 65536
#define N_DIM 41
#define G_DIM 2048
#define O_DIM 256
#define E_DIM 512
#define NO_DIM (N_DIM * O_DIM)
#define NEG_SLOPE 0.2f

// statics ~59 MB
__device__ unsigned short g_xT[(size_t)D_DIM * B_DIM];     // 32 MB fp16 bits
__device__ unsigned short g_H[(size_t)B_DIM * NO_DIM];     // 5.4 MB fp16 bits
__device__ float g_P[(size_t)N_DIM * B_DIM * E_DIM];       // 21.5 MB

// ---------------------------------------------------------------- helpers
__device__ __forceinline__ uint32_t sptr(const void* p) {
    return (uint32_t)__cvta_generic_to_shared(p);
}
__device__ __forceinline__ void ldsm4t(uint32_t* r, uint32_t a) {
    asm volatile("ldmatrix.sync.aligned.m8n8.x4.trans.shared.b16 {%0,%1,%2,%3},[%4];"
                 : "=r"(r[0]), "=r"(r[1]), "=r"(r[2]), "=r"(r[3]) : "r"(a));
}
__device__ __forceinline__ void ldsm4(uint32_t* r, uint32_t a) {
    asm volatile("ldmatrix.sync.aligned.m8n8.x4.shared.b16 {%0,%1,%2,%3},[%4];"
                 : "=r"(r[0]), "=r"(r[1]), "=r"(r[2]), "=r"(r[3]) : "r"(a));
}
__device__ __forceinline__ void mma16816h(float* c, const uint32_t* a, const uint32_t* b) {
    asm volatile("mma.sync.aligned.m16n8k16.row.col.f32.f16.f16.f32 "
                 "{%0,%1,%2,%3},{%4,%5,%6,%7},{%8,%9},{%0,%1,%2,%3};"
                 : "+f"(c[0]), "+f"(c[1]), "+f"(c[2]), "+f"(c[3])
                 : "r"(a[0]), "r"(a[1]), "r"(a[2]), "r"(a[3]), "r"(b[0]), "r"(b[1]));
}
__device__ __forceinline__ uint32_t pack2h(float a, float b) {
    return (uint32_t)__half_as_ushort(__float2half_rn(a)) |
           ((uint32_t)__half_as_ushort(__float2half_rn(b)) << 16);
}

// ---------------------------------------------------------------- transpose x -> fp16 xT [D][B]
__global__ __launch_bounds__(256) void transpose_kernel(const float* __restrict__ x) {
    __shared__ float tile[64][65];
    int d0 = blockIdx.x * 64, b0 = blockIdx.y * 64;
    int t = threadIdx.x;
    int br = t / 16, dc = (t % 16) * 4;
#pragma unroll
    for (int p = 0; p < 4; p++) {
        int b = br + p * 16;
        float4 v = *(const float4*)&x[(size_t)(b0 + b) * D_DIM + d0 + dc];
        tile[b][dc] = v.x; tile[b][dc+1] = v.y; tile[b][dc+2] = v.z; tile[b][dc+3] = v.w;
    }
    __syncthreads();
    int dr = t / 16, bc = (t % 16) * 4;
#pragma unroll
    for (int p = 0; p < 4; p++) {
        int d = dr + p * 16;
        size_t off = (size_t)(d0 + d) * B_DIM + b0 + bc;
        *(uint2*)&g_xT[off] = make_uint2(pack2h(tile[bc][d],   tile[bc+1][d]),
                                         pack2h(tile[bc+2][d], tile[bc+3][d]));
    }
}

// ---------------------------------------------------------------- GEMM1 (fp16 1-term, tile 128x64, BK=32, prefetch-2, occ 2)
// H[b][n*256+o] = sum_g xT[idx][b] * W[n][g][o] + bias
__global__ __launch_bounds__(256, 2) void gemm1_kernel(
    const int* __restrict__ gidx, const float* __restrict__ W, const float* __restrict__ bias)
{
    __shared__ unsigned short sIdx[G_DIM];                      // 4 KB
    __shared__ alignas(16) unsigned short As[2][32][136];       // 17.4 KB
    __shared__ alignas(16) unsigned short Bs[2][32][72];        // 9.2 KB

    const int n     = blockIdx.z;
    const int bbase = blockIdx.x * 128;
    const int obase = blockIdx.y * 64;
    const int tid = threadIdx.x, lane = tid & 31, warp = tid >> 5;
    const int wm = (warp & 1) * 64, wn = (warp >> 1) * 16;
    const int arow = tid >> 3, acol = (tid & 7) * 8;    // A: 32 rows x (2x 8-half chunks)
    const int brow = tid >> 3, bcol = (tid & 7) * 4;    // B: 32 rows x (2x float4)

    for (int i = tid; i < G_DIM; i += 256)
        sIdx[i] = (unsigned short)gidx[(size_t)n * G_DIM + i];
    __syncthreads();

    const float* Wn = W + (size_t)n * G_DIM * O_DIM;
    const int g8 = lane >> 3, i8 = lane & 7;
    const int a_krow = (g8 >> 1) * 8 + i8, a_mcol = (g8 & 1) * 8;
    const int b_krow = (g8 & 1) * 8 + i8, b_ncol = (g8 >> 1) * 8;

    float acc[4][2][4];
#pragma unroll
    for (int i = 0; i < 4; i++)
#pragma unroll
        for (int j = 0; j < 2; j++)
#pragma unroll
            for (int q = 0; q < 4; q++) acc[i][j][q] = 0.0f;

    auto ldg = [&](int ch, uint4& a0, uint4& a1, float4& w0, float4& w1) {
        int k0 = ch * 32;
        int gi = sIdx[k0 + arow];
        const unsigned short* xr = &g_xT[(size_t)gi * B_DIM + bbase + acol];
        a0 = *(const uint4*)xr;
        a1 = *(const uint4*)(xr + 64);
        const float* wr = &Wn[(size_t)(k0 + brow) * O_DIM + obase + bcol];
        w0 = *(const float4*)wr;
        w1 = *(const float4*)(wr + 32);
    };
    auto sts = [&](int buf, uint4 a0, uint4 a1, float4 w0, float4 w1) {
        *(uint4*)&As[buf][arow][acol]      = a0;
        *(uint4*)&As[buf][arow][acol + 64] = a1;
        *(uint2*)&Bs[buf][brow][bcol]      = make_uint2(pack2h(w0.x, w0.y), pack2h(w0.z, w0.w));
        *(uint2*)&Bs[buf][brow][bcol + 32] = make_uint2(pack2h(w1.x, w1.y), pack2h(w1.z, w1.w));
    };
    auto compute = [&](int buf) {
#pragma unroll
        for (int ks = 0; ks < 2; ks++) {
            uint32_t af[4][4], bf[4];
#pragma unroll
            for (int mt = 0; mt < 4; mt++)
                ldsm4t(af[mt], sptr(&As[buf][ks * 16 + a_krow][wm + mt * 16 + a_mcol]));
            ldsm4t(bf, sptr(&Bs[buf][ks * 16 + b_krow][wn + b_ncol]));
#pragma unroll
            for (int mt = 0; mt < 4; mt++)
#pragma unroll
                for (int nt = 0; nt < 2; nt++)
                    mma16816h(acc[mt][nt], af[mt], &bf[nt * 2]);
        }
    };

    uint4 A00, A01, A10, A11;
    float4 W00, W01, W10, W11;
    ldg(0, A00, A01, W00, W01);
    sts(0, A00, A01, W00, W01);
    ldg(1, A00, A01, W00, W01);
    __syncthreads();

    const int NCHUNK = G_DIM / 32;  // 64
    for (int ch = 0; ch < NCHUNK; ch += 2) {
        if (ch + 2 < NCHUNK) ldg(ch + 2, A10, A11, W10, W11);
        compute(0);
        sts(1, A00, A01, W00, W01);
        __syncthreads();
        if (ch + 3 < NCHUNK) ldg(ch + 3, A00, A01, W00, W01);
        compute(1);
        if (ch + 2 < NCHUNK) sts(0, A10, A11, W10, W11);
        __syncthreads();
    }

    // epilogue: H -> fp16, row-major [B][NO]
    const int r = lane >> 2, c = (lane & 3) * 2;
#pragma unroll
    for (int mt = 0; mt < 4; mt++)
#pragma unroll
        for (int nt = 0; nt < 2; nt++) {
            int ocol = obase + wn + nt * 8 + c;
            float bv0 = bias[n * O_DIM + ocol], bv1 = bias[n * O_DIM + ocol + 1];
            int b0 = bbase + wm + mt * 16 + r;
#pragma unroll
            for (int q = 0; q < 2; q++) {
                size_t base = (size_t)(b0 + q*8) * NO_DIM + (size_t)n * O_DIM + ocol;
                *(uint32_t*)&g_H[base] =
                    pack2h(acc[mt][nt][q*2] + bv0, acc[mt][nt][q*2+1] + bv1);
            }
        }
}

// ---------------------------------------------------------------- GEMM2 split-K (fp16 1-term, BK=16, prefetch-2, occ 2)
__global__ __launch_bounds__(256, 2) void gemm2_kernel(const float* __restrict__ W3)
{
    __shared__ alignas(16) unsigned short As[2][128][24];   // 12 KB
    __shared__ alignas(16) unsigned short Bs[2][16][136];   // 8.5 KB

    const int s = blockIdx.z, bbase = blockIdx.x * 128, ebase = blockIdx.y * 128;
    const int tid = threadIdx.x, lane = tid & 31, warp = tid >> 5;
    const int wm = (warp & 1) * 64, wn = (warp >> 1) * 32;
    const int arow = tid >> 1, ahalf = (tid & 1) * 8;
    const int kkB = tid >> 5, colB = (tid & 31) * 4;
    const int g8 = lane >> 3, i8 = lane & 7;
    const int a_mrow = (g8 & 1) * 8 + i8, a_kcol = (g8 >> 1) * 8;
    const int b_krow = (g8 & 1) * 8 + i8, b_ncol = (g8 >> 1) * 8;

    float acc[4][4][4];
#pragma unroll
    for (int i = 0; i < 4; i++)
#pragma unroll
        for (int j = 0; j < 4; j++)
#pragma unroll
            for (int q = 0; q < 4; q++) acc[i][j][q] = 0.0f;

    const int kbeg = s * 256;

    auto ldg = [&](int ch, uint4& ah, float4& p0, float4& p1) {
        int k0 = kbeg + ch * 16;
        ah = *(const uint4*)&g_H[(size_t)(bbase + arow) * NO_DIM + k0 + ahalf];
        p0 = *(const float4*)&W3[(size_t)(k0 + kkB) * E_DIM + ebase + colB];
        p1 = *(const float4*)&W3[(size_t)(k0 + kkB + 8) * E_DIM + ebase + colB];
    };
    auto sts = [&](int buf, uint4 ah, float4 p0, float4 p1) {
        *(uint4*)&As[buf][arow][ahalf] = ah;
        *(uint2*)&Bs[buf][kkB][colB]     = make_uint2(pack2h(p0.x, p0.y), pack2h(p0.z, p0.w));
        *(uint2*)&Bs[buf][kkB + 8][colB] = make_uint2(pack2h(p1.x, p1.y), pack2h(p1.z, p1.w));
    };
    auto compute = [&](int buf) {
        uint32_t af[4][4], bfv[2][4];
#pragma unroll
        for (int mt = 0; mt < 4; mt++)
            ldsm4(af[mt], sptr(&As[buf][wm + mt * 16 + a_mrow][a_kcol]));
#pragma unroll
        for (int np = 0; np < 2; np++)
            ldsm4t(bfv[np], sptr(&Bs[buf][b_krow][wn + np * 16 + b_ncol]));
#pragma unroll
        for (int mt = 0; mt < 4; mt++)
#pragma unroll
            for (int nt = 0; nt < 4; nt++)
                mma16816h(acc[mt][nt], af[mt], &bfv[nt >> 1][(nt & 1) * 2]);
    };

    uint4 Ah0, Ah1;
    float4 B00, B01, B10, B11;
    ldg(0, Ah0, B00, B01);
    sts(0, Ah0, B00, B01);
    ldg(1, Ah0, B00, B01);
    __syncthreads();

    const int NCHUNK = 16;
    for (int ch = 0; ch < NCHUNK; ch += 2) {
        if (ch + 2 < NCHUNK) ldg(ch + 2, Ah1, B10, B11);
        compute(0);
        sts(1, Ah0, B00, B01);
        __syncthreads();
        if (ch + 3 < NCHUNK) ldg(ch + 3, Ah0, B00, B01);
        compute(1);
        if (ch + 2 < NCHUNK) sts(0, Ah1, B10, B11);
        __syncthreads();
    }

    float* Ps = g_P + (size_t)s * B_DIM * E_DIM;
    const int r = lane >> 2, c = (lane & 3) * 2;
#pragma unroll
    for (int mt = 0; mt < 4; mt++)
#pragma unroll
        for (int nt = 0; nt < 4; nt++) {
            int ecol = ebase + wn + nt * 8 + c;
            int b0 = bbase + wm + mt * 16 + r;
            *(float2*)&Ps[(size_t)b0 * E_DIM + ecol] = make_float2(acc[mt][nt][0], acc[mt][nt][1]);
            *(float2*)&Ps[(size_t)(b0 + 8) * E_DIM + ecol] = make_float2(acc[mt][nt][2], acc[mt][nt][3]);
        }
}

// ---------------------------------------------------------------- reduce
__global__ __launch_bounds__(256) void reduce_kernel(const float* __restrict__ b3, float* __restrict__ out) {
    int i4 = blockIdx.x * 256 + threadIdx.x;
    int e4 = i4 & (E_DIM / 4 - 1);
    float4 sum = ((const float4*)b3)[e4];
#pragma unroll
    for (int s = 0; s < N_DIM; s++) {
        float4 p = ((const float4*)g_P)[(size_t)s * (B_DIM * E_DIM / 4) + i4];
        sum.x += p.x; sum.y += p.y; sum.z += p.z; sum.w += p.w;
    }
    sum.x = (sum.x >= 0.f) ? sum.x : NEG_SLOPE * sum.x;
    sum.y = (sum.y >= 0.f) ? sum.y : NEG_SLOPE * sum.y;
    sum.z = (sum.z >= 0.f) ? sum.z : NEG_SLOPE * sum.z;
    sum.w = (sum.w >= 0.f) ? sum.w : NEG_SLOPE * sum.w;
    ((float4*)out)[i4] = sum;
}

// ----------------------------------------------------------------
extern "C" void kernel_launch(void* const* d_in, const int* in_sizes, int n_in,
                              void* d_out, int out_size) {
    const float* x    = (const float*)d_in[0];
    const int*   gidx = (const int*)  d_in[1];
    const float* W    = (const float*)d_in[2];
    const float* bias = (const float*)d_in[3];
    const float* W3   = (const float*)d_in[4];
    const float* b3   = (const float*)d_in[5];
    float* out = (float*)d_out;

    {
        dim3 grid(D_DIM / 64, B_DIM / 64);
        transpose_kernel<<<grid, 256>>>(x);
    }
    {
        dim3 grid(B_DIM / 128, O_DIM / 64, N_DIM);    // (2,4,41) = 328 CTAs
        gemm1_kernel<<<grid, 256>>>(gidx, W, bias);
    }
    {
        dim3 grid(B_DIM / 128, E_DIM / 128, N_DIM);   // (2,4,41)
        gemm2_kernel<<<grid, 256>>>(W3);
    }
    {
        reduce_kernel<<<(B_DIM * E_DIM / 4) / 256, 256>>>(b3, out);
    }
}